// round 5
// baseline (speedup 1.0000x reference)
#include <cuda_runtime.h>
#include <cuda_bf16.h>
#include <math_constants.h>
#include <stdint.h>

#define BATCH 4
#define SEQ   2048
#define DM    1024
#define MROWS (BATCH * SEQ)
#define NQKV  (3 * DM)                  // 3072

// ---- GEMM tiling ----------------------------------------------------------
#define TM 128
#define TN 256
#define BK 64                           // bf16 per K-chunk (128 B rows)
#define TILE_A (TM * 128)               // 16 KB
#define TILE_B (TN * 128)               // 32 KB
#define STAGE_BYTES (2 * TILE_A + 2 * TILE_B)   // Ahi,Alo,Bhi,Blo = 96 KB
#define SMEM_DYN (2 * STAGE_BYTES)              // 192 KB

typedef __nv_bfloat16 bf16;

// ---- scratch (static __device__: allocation-free) ---------------------------
#define AL1K __align__(1024)
__device__ AL1K bf16  g_xh  [MROWS * DM];
__device__ AL1K bf16  g_xl  [MROWS * DM];
__device__ AL1K bf16  g_wh  [NQKV * DM];          // [Wq^T;Wk^T;Wv^T] hi
__device__ AL1K bf16  g_wl  [NQKV * DM];
__device__ AL1K float g_bqkv[NQKV];
__device__ AL1K bf16  g_woh [DM * DM];
__device__ AL1K bf16  g_wol [DM * DM];
__device__ AL1K bf16  g_qkvh[(size_t)MROWS * NQKV];   // [B*S][3D]
__device__ AL1K bf16  g_qkvl[(size_t)MROWS * NQKV];
__device__ AL1K bf16  g_vth [MROWS * DM];             // [B][D][S]
__device__ AL1K bf16  g_vtl [MROWS * DM];
__device__ AL1K float g_p   [(size_t)BATCH * SEQ * SEQ];
__device__ AL1K bf16  g_ph  [(size_t)BATCH * SEQ * SEQ];
__device__ AL1K bf16  g_pl  [(size_t)BATCH * SEQ * SEQ];
__device__ AL1K bf16  g_aoh [MROWS * DM];
__device__ AL1K bf16  g_aol [MROWS * DM];

// ---- PTX helpers ------------------------------------------------------------
__device__ __forceinline__ uint32_t s2u(const void* p) {
    uint32_t a;
    asm("{ .reg .u64 t; cvta.to.shared.u64 t, %1; cvt.u32.u64 %0, t; }" : "=r"(a) : "l"(p));
    return a;
}
__device__ __forceinline__ void cp16(uint32_t saddr, const void* gaddr) {
    asm volatile("cp.async.cg.shared.global [%0], [%1], 16;" :: "r"(saddr), "l"(gaddr));
}
__device__ __forceinline__ void cp_commit() { asm volatile("cp.async.commit_group;"); }
__device__ __forceinline__ void cp_wait1()  { asm volatile("cp.async.wait_group 1;" ::: "memory"); }

__device__ __forceinline__ void ldm4(uint32_t* r, uint32_t addr) {
    asm volatile("ldmatrix.sync.aligned.m8n8.x4.shared.b16 {%0,%1,%2,%3}, [%4];"
                 : "=r"(r[0]), "=r"(r[1]), "=r"(r[2]), "=r"(r[3]) : "r"(addr));
}
__device__ __forceinline__ void mma16816(float* c, const uint32_t* a, const uint32_t* b) {
    asm volatile(
        "mma.sync.aligned.m16n8k16.row.col.f32.bf16.bf16.f32 "
        "{%0,%1,%2,%3}, {%4,%5,%6,%7}, {%8,%9}, {%0,%1,%2,%3};"
        : "+f"(c[0]), "+f"(c[1]), "+f"(c[2]), "+f"(c[3])
        : "r"(a[0]), "r"(a[1]), "r"(a[2]), "r"(a[3]), "r"(b[0]), "r"(b[1]));
}
__device__ __forceinline__ uint32_t pk2(float a, float b) {
    __nv_bfloat162 t = __floats2bfloat162_rn(a, b);
    return *reinterpret_cast<uint32_t*>(&t);
}

// ============================================================================
// Tensor-core GEMM: C[M,N] = scale*((Ahi+Alo)[M,K] @ ((Bhi+Blo)[N,K])^T)+bias
//   CTA tile 128x256, warp tile 64x64, 8 warps, 2-stage cp.async (96KB/stage).
//   3-term split product: Ahi*Bhi + Ahi*Blo + Alo*Bhi (fp32 accum).
//   OUTMODE 0: fp32 out. OUTMODE 1: bf16 hi/lo split out.
//   CAUSAL: skip tiles with n0 > m0+TM-1.  PVLIM: nchunk=(m0+TM)/BK.
// ============================================================================
template<int OUTMODE, bool HAS_BIAS, bool CAUSAL, bool PVLIM>
__global__ __launch_bounds__(256, 1)
void tc_gemm(const bf16* __restrict__ Ah, const bf16* __restrict__ Al,
             const bf16* __restrict__ Bh, const bf16* __restrict__ Bl,
             const float* __restrict__ bias,
             float* __restrict__ Cf, bf16* __restrict__ Ch, bf16* __restrict__ Cl,
             int Kfull, int ldA, int ldB, int ldC, float scale,
             size_t sA, size_t sB, size_t sC)
{
    const int m0 = blockIdx.y * TM;
    const int n0 = blockIdx.x * TN;
    if (CAUSAL && n0 > m0 + TM - 1) return;

    const int z = blockIdx.z;
    Ah += (size_t)z * sA;  Al += (size_t)z * sA;
    Bh += (size_t)z * sB;  Bl += (size_t)z * sB;

    extern __shared__ char dsm[];
    const uint32_t smem = s2u(dsm);

    const int tid  = threadIdx.x;
    const int wid  = tid >> 5;
    const int lane = tid & 31;
    const int wm   = wid & 1;      // 2 warp-rows  (64 M each)
    const int wn   = wid >> 1;     // 4 warp-cols  (64 N each)

    const int nchunk = PVLIM ? (m0 + TM) / BK : Kfull / BK;

    // ---- loader: 768 rows of 128B per stage, 3 rows per thread --------------
    const char* gp[3];
    uint32_t    sb[3];
    uint32_t    swz[3];
    #pragma unroll
    for (int rr = 0; rr < 3; rr++) {
        const int row = tid + rr * 256;
        const bf16* base;
        int lr, ld, off;
        uint32_t so;
        if (row < 128)      { base = Ah; lr = row;       ld = ldA; off = m0; so = (uint32_t)lr * 128; }
        else if (row < 256) { base = Al; lr = row - 128; ld = ldA; off = m0; so = TILE_A + (uint32_t)lr * 128; }
        else if (row < 512) { base = Bh; lr = row - 256; ld = ldB; off = n0; so = 2 * TILE_A + (uint32_t)lr * 128; }
        else                { base = Bl; lr = row - 512; ld = ldB; off = n0; so = 2 * TILE_A + TILE_B + (uint32_t)lr * 128; }
        gp[rr]  = (const char*)(base + (size_t)(off + lr) * ld);
        sb[rr]  = so;
        swz[rr] = (uint32_t)(lr & 7);
    }

    auto load_stage = [&](int slot, int chunk) {
        if (chunk < nchunk) {
            const uint32_t s0 = smem + slot * STAGE_BYTES;
            const size_t goff = (size_t)chunk * 128;     // 64 bf16 = 128 B
            #pragma unroll
            for (int rr = 0; rr < 3; rr++) {
                const char* g = gp[rr] + goff;
                const uint32_t sr = s0 + sb[rr];
                #pragma unroll
                for (uint32_t seg = 0; seg < 8; seg++)
                    cp16(sr + ((seg ^ swz[rr]) << 4), g + seg * 16);
            }
        }
        cp_commit();
    };

    float acc[4][8][4];
    #pragma unroll
    for (int a = 0; a < 4; a++)
        #pragma unroll
        for (int b = 0; b < 8; b++)
            #pragma unroll
            for (int c = 0; c < 4; c++) acc[a][b][c] = 0.f;

    load_stage(0, 0);
    load_stage(1, 1);

    // fragment address components (constant per thread)
    const int a_r  = lane & 15;
    const int a_kh = lane >> 4;
    const int b_nl = ((lane >> 4) & 1) * 8 + (lane & 7);
    const int b_kh = (lane >> 3) & 1;

    for (int i = 0; i < nchunk; i++) {
        cp_wait1();
        __syncthreads();
        const uint32_t s0 = smem + (i & 1) * STAGE_BYTES;

        #pragma unroll
        for (int kk = 0; kk < 4; kk++) {
            uint32_t ahf[4][4], alf[4][4], bhf[4][4], blf[4][4];
            #pragma unroll
            for (int mt = 0; mt < 4; mt++) {
                const int row = wm * 64 + mt * 16 + a_r;
                const uint32_t off =
                    (uint32_t)(row * 128) + ((((kk * 2 + a_kh)) ^ (a_r & 7)) << 4);
                ldm4(ahf[mt], s0 + off);
                ldm4(alf[mt], s0 + TILE_A + off);
            }
            #pragma unroll
            for (int p = 0; p < 4; p++) {
                const int row = wn * 64 + p * 16 + b_nl;
                const uint32_t off =
                    (uint32_t)(row * 128) + ((((kk * 2 + b_kh)) ^ (b_nl & 7)) << 4);
                ldm4(bhf[p], s0 + 2 * TILE_A + off);
                ldm4(blf[p], s0 + 2 * TILE_A + TILE_B + off);
            }
            #pragma unroll
            for (int mt = 0; mt < 4; mt++) {
                #pragma unroll
                for (int nt = 0; nt < 8; nt++) {
                    const int p = nt >> 1, o = (nt & 1) * 2;
                    mma16816(acc[mt][nt], ahf[mt], &bhf[p][o]);
                    mma16816(acc[mt][nt], ahf[mt], &blf[p][o]);
                    mma16816(acc[mt][nt], alf[mt], &bhf[p][o]);
                }
            }
        }
        __syncthreads();
        load_stage(i & 1, i + 2);
    }

    // ---- epilogue -------------------------------------------------------------
    #pragma unroll
    for (int mt = 0; mt < 4; mt++) {
        #pragma unroll
        for (int h = 0; h < 2; h++) {
            const int row = m0 + wm * 64 + mt * 16 + (lane >> 2) + 8 * h;
            #pragma unroll
            for (int nt = 0; nt < 8; nt++) {
                const int col = n0 + wn * 64 + nt * 8 + (lane & 3) * 2;
                float v0 = acc[mt][nt][2 * h + 0] * scale;
                float v1 = acc[mt][nt][2 * h + 1] * scale;
                if (HAS_BIAS) {
                    const float2 bb = *reinterpret_cast<const float2*>(bias + col);
                    v0 += bb.x; v1 += bb.y;
                }
                if (OUTMODE == 0) {
                    *reinterpret_cast<float2*>(
                        Cf + (size_t)z * sC + (size_t)row * ldC + col) =
                        make_float2(v0, v1);
                } else {
                    float h0 = __bfloat162float(__float2bfloat16(v0));
                    float h1 = __bfloat162float(__float2bfloat16(v1));
                    *reinterpret_cast<uint32_t*>(
                        Ch + (size_t)z * sC + (size_t)row * ldC + col) = pk2(h0, h1);
                    *reinterpret_cast<uint32_t*>(
                        Cl + (size_t)z * sC + (size_t)row * ldC + col) =
                        pk2(v0 - h0, v1 - h1);
                }
            }
        }
    }
}

// ============================================================================
// prep kernels
// ============================================================================
__global__ void split_kernel(const float* __restrict__ in,
                             bf16* __restrict__ oh, bf16* __restrict__ ol, int n)
{
    int i = blockIdx.x * blockDim.x + threadIdx.x;
    if (i >= n) return;
    float v = in[i];
    bf16 h = __float2bfloat16(v);
    oh[i] = h;
    ol[i] = __float2bfloat16(v - __bfloat162float(h));
}

// transpose + split: in [R,C] fp32 -> out hi/lo [C,R] bf16
__global__ void tsplit_kernel(const float* __restrict__ in,
                              bf16* __restrict__ oh, bf16* __restrict__ ol,
                              int R, int C)
{
    __shared__ float t[32][33];
    const int c0 = blockIdx.x * 32, r0 = blockIdx.y * 32;
    const int tx = threadIdx.x, ty = threadIdx.y;
    #pragma unroll
    for (int k = 0; k < 4; k++)
        t[ty + 8 * k][tx] = in[(size_t)(r0 + ty + 8 * k) * C + c0 + tx];
    __syncthreads();
    #pragma unroll
    for (int k = 0; k < 4; k++) {
        float v = t[tx][ty + 8 * k];
        bf16 h = __float2bfloat16(v);
        size_t o = (size_t)(c0 + ty + 8 * k) * R + r0 + tx;
        oh[o] = h;
        ol[o] = __float2bfloat16(v - __bfloat162float(h));
    }
}

// V transpose+split from the combined QKV split output.
// reads v = hi+lo at [z*SEQ+s][2048+d] (ld NQKV) -> vth/vtl [z][d][s]
__global__ void vtsplit_kernel(const bf16* __restrict__ qh, const bf16* __restrict__ ql,
                               bf16* __restrict__ oh, bf16* __restrict__ ol)
{
    __shared__ float t[32][33];
    const int z = blockIdx.z;
    const int d0 = blockIdx.x * 32, s0 = blockIdx.y * 32;
    const int tx = threadIdx.x, ty = threadIdx.y;
    #pragma unroll
    for (int k = 0; k < 4; k++) {
        size_t idx = (size_t)(z * SEQ + s0 + ty + 8 * k) * NQKV + 2 * DM + d0 + tx;
        t[ty + 8 * k][tx] = __bfloat162float(qh[idx]) + __bfloat162float(ql[idx]);
    }
    __syncthreads();
    #pragma unroll
    for (int k = 0; k < 4; k++) {
        float v = t[tx][ty + 8 * k];
        bf16 h = __float2bfloat16(v);
        size_t o = (size_t)z * DM * SEQ + (size_t)(d0 + ty + 8 * k) * SEQ + s0 + tx;
        oh[o] = h;
        ol[o] = __float2bfloat16(v - __bfloat162float(h));
    }
}

__global__ void bias_concat_kernel(const float* a, const float* b, const float* c,
                                   float* o)
{
    int i = blockIdx.x * blockDim.x + threadIdx.x;
    if (i >= NQKV) return;
    o[i] = (i < DM) ? a[i] : (i < 2 * DM ? b[i - DM] : c[i - 2 * DM]);
}

// causal softmax: fp32 scores -> split bf16 weights, zero-fill to 128 boundary
__global__ __launch_bounds__(256)
void softmax_split_kernel(float* __restrict__ P,
                          bf16* __restrict__ Ph, bf16* __restrict__ Pl)
{
    const int rowi = blockIdx.x;
    const int b = rowi / SEQ, q = rowi % SEQ;
    const size_t off = (size_t)b * SEQ * SEQ + (size_t)q * SEQ;
    float* p = P + off;
    bf16* ph = Ph + off;
    bf16* pl = Pl + off;
    const int n = q + 1;

    __shared__ float red[256];
    const int tid = threadIdx.x;

    float mx = -CUDART_INF_F;
    for (int k = tid; k < n; k += 256) mx = fmaxf(mx, p[k]);
    red[tid] = mx; __syncthreads();
    #pragma unroll
    for (int s = 128; s > 0; s >>= 1) {
        if (tid < s) red[tid] = fmaxf(red[tid], red[tid + s]);
        __syncthreads();
    }
    mx = red[0]; __syncthreads();

    float sum = 0.f;
    for (int k = tid; k < n; k += 256) {
        float e = expf(p[k] - mx);
        p[k] = e;
        sum += e;
    }
    red[tid] = sum; __syncthreads();
    #pragma unroll
    for (int s = 128; s > 0; s >>= 1) {
        if (tid < s) red[tid] += red[tid + s];
        __syncthreads();
    }
    const float inv = 1.f / red[0];

    for (int k = tid; k < n; k += 256) {
        float w = p[k] * inv;
        bf16 h = __float2bfloat16(w);
        ph[k] = h;
        pl[k] = __float2bfloat16(w - __bfloat162float(h));
    }
    const int fillEnd = ((q >> 7) + 1) << 7;
    for (int k = n + tid; k < fillEnd; k += 256) {
        ph[k] = __float2bfloat16(0.f);
        pl[k] = __float2bfloat16(0.f);
    }
}

// ============================================================================
extern "C" void kernel_launch(void* const* d_in, const int*, int, void* d_out, int)
{
    const float* x  = (const float*)d_in[0];
    const float* Wq = (const float*)d_in[1];
    const float* bq = (const float*)d_in[2];
    const float* Wk = (const float*)d_in[3];
    const float* bk = (const float*)d_in[4];
    const float* Wv = (const float*)d_in[5];
    const float* bv = (const float*)d_in[6];
    const float* Wo = (const float*)d_in[7];
    const float* bo = (const float*)d_in[8];
    float* out = (float*)d_out;

    bf16 *xh, *xl, *wh, *wl, *woh, *wol, *qkvh, *qkvl, *vth, *vtl, *phh, *pll, *aoh, *aol;
    float *p, *bqkv;
    cudaGetSymbolAddress((void**)&xh,   g_xh);   cudaGetSymbolAddress((void**)&xl,   g_xl);
    cudaGetSymbolAddress((void**)&wh,   g_wh);   cudaGetSymbolAddress((void**)&wl,   g_wl);
    cudaGetSymbolAddress((void**)&bqkv, g_bqkv);
    cudaGetSymbolAddress((void**)&woh,  g_woh);  cudaGetSymbolAddress((void**)&wol,  g_wol);
    cudaGetSymbolAddress((void**)&qkvh, g_qkvh); cudaGetSymbolAddress((void**)&qkvl, g_qkvl);
    cudaGetSymbolAddress((void**)&vth,  g_vth);  cudaGetSymbolAddress((void**)&vtl,  g_vtl);
    cudaGetSymbolAddress((void**)&p,    g_p);
    cudaGetSymbolAddress((void**)&phh,  g_ph);   cudaGetSymbolAddress((void**)&pll,  g_pl);
    cudaGetSymbolAddress((void**)&aoh,  g_aoh);  cudaGetSymbolAddress((void**)&aol,  g_aol);

    cudaFuncSetAttribute(tc_gemm<1, true,  false, false>, cudaFuncAttributeMaxDynamicSharedMemorySize, SMEM_DYN);
    cudaFuncSetAttribute(tc_gemm<0, true,  false, false>, cudaFuncAttributeMaxDynamicSharedMemorySize, SMEM_DYN);
    cudaFuncSetAttribute(tc_gemm<0, false, true,  false>, cudaFuncAttributeMaxDynamicSharedMemorySize, SMEM_DYN);
    cudaFuncSetAttribute(tc_gemm<1, false, false, true >, cudaFuncAttributeMaxDynamicSharedMemorySize, SMEM_DYN);

    // ---- prep ---------------------------------------------------------------
    split_kernel<<<(MROWS * DM + 255) / 256, 256>>>(x, xh, xl, MROWS * DM);
    {
        dim3 blk(32, 8), grid(DM / 32, DM / 32);
        tsplit_kernel<<<grid, blk>>>(Wq, wh,                wl,                DM, DM);
        tsplit_kernel<<<grid, blk>>>(Wk, wh + DM * DM,      wl + DM * DM,      DM, DM);
        tsplit_kernel<<<grid, blk>>>(Wv, wh + 2 * DM * DM,  wl + 2 * DM * DM,  DM, DM);
        tsplit_kernel<<<grid, blk>>>(Wo, woh,               wol,               DM, DM);
    }
    bias_concat_kernel<<<(NQKV + 255) / 256, 256>>>(bq, bk, bv, bqkv);

    // ---- fused QKV projection: [8192,1024] @ [1024,3072] + b ----------------
    {
        dim3 grid(NQKV / TN, MROWS / TM, 1), blk(256);
        tc_gemm<1, true, false, false><<<grid, blk, SMEM_DYN>>>(
            xh, xl, wh, wl, bqkv, nullptr, qkvh, qkvl,
            DM, DM, DM, NQKV, 1.f, 0, 0, 0);
    }

    // ---- V transpose+split ---------------------------------------------------
    {
        dim3 blk(32, 8), grid(DM / 32, SEQ / 32, BATCH);
        vtsplit_kernel<<<grid, blk>>>(qkvh, qkvl, vth, vtl);
    }

    // ---- scores = Q @ K^T / 8 (causal tile skip) -----------------------------
    {
        dim3 grid(SEQ / TN, SEQ / TM, BATCH), blk(256);
        tc_gemm<0, false, true, false><<<grid, blk, SMEM_DYN>>>(
            qkvh, qkvl, qkvh + DM, qkvl + DM, nullptr, p, nullptr, nullptr,
            DM, NQKV, NQKV, SEQ, 0.125f,
            (size_t)SEQ * NQKV, (size_t)SEQ * NQKV, (size_t)SEQ * SEQ);
    }

    // ---- softmax --------------------------------------------------------------
    softmax_split_kernel<<<MROWS, 256>>>(p, phh, pll);

    // ---- attn_out = P @ V (K truncated at causal boundary) --------------------
    {
        dim3 grid(DM / TN, SEQ / TM, BATCH), blk(256);
        tc_gemm<1, false, false, true><<<grid, blk, SMEM_DYN>>>(
            phh, pll, vth, vtl, nullptr, nullptr, aoh, aol,
            SEQ, SEQ, SEQ, DM, 1.f,
            (size_t)SEQ * SEQ, (size_t)DM * SEQ, (size_t)SEQ * DM);
    }

    // ---- out = attn_out @ Wo + bo ---------------------------------------------
    {
        dim3 grid(DM / TN, MROWS / TM, 1), blk(256);
        tc_gemm<0, true, false, false><<<grid, blk, SMEM_DYN>>>(
            aoh, aol, woh, wol, bo, out, nullptr, nullptr,
            DM, DM, DM, DM, 1.f, 0, 0, 0);
    }
}

// round 6
// speedup vs baseline: 1.2748x; 1.2748x over previous
#include <cuda_runtime.h>
#include <cuda_bf16.h>
#include <math_constants.h>
#include <stdint.h>

#define BATCH 4
#define SEQ   2048
#define DM    1024
#define MROWS (BATCH * SEQ)
#define NQKV  (3 * DM)                // 3072

// ---- GEMM tiling (round-4 proven config) -----------------------------------
#define TM 128
#define TN 128
#define BK 64                         // bf16 elems per K-chunk (128 bytes/row)
#define TILE_BYTES (128 * 128)        // 16 KB per operand tile
#define STAGE_BYTES (4 * TILE_BYTES)  // Ahi,Alo,Bhi,Blo = 64 KB
#define NSTAGE 3
#define SMEM_DYN (NSTAGE * STAGE_BYTES)   // 192 KB

typedef __nv_bfloat16 bf16;

// ---- scratch (static __device__: allocation-free) ---------------------------
#define AL1K __align__(1024)
__device__ AL1K bf16  g_xh  [MROWS * DM];
__device__ AL1K bf16  g_xl  [MROWS * DM];
__device__ AL1K bf16  g_wh  [NQKV * DM];              // [Wq^T;Wk^T;Wv^T] hi
__device__ AL1K bf16  g_wl  [NQKV * DM];
__device__ AL1K float g_bqkv[NQKV];
__device__ AL1K bf16  g_woh [DM * DM];
__device__ AL1K bf16  g_wol [DM * DM];
__device__ AL1K bf16  g_qkvh[(size_t)MROWS * NQKV];   // [B*S][3D]
__device__ AL1K bf16  g_qkvl[(size_t)MROWS * NQKV];
__device__ AL1K bf16  g_vth [MROWS * DM];             // [B][D][S]
__device__ AL1K bf16  g_vtl [MROWS * DM];
__device__ AL1K float g_p   [(size_t)BATCH * SEQ * SEQ];
__device__ AL1K bf16  g_ph  [(size_t)BATCH * SEQ * SEQ];
__device__ AL1K bf16  g_pl  [(size_t)BATCH * SEQ * SEQ];
__device__ AL1K bf16  g_aoh [MROWS * DM];
__device__ AL1K bf16  g_aol [MROWS * DM];

// ---- PTX helpers (plain sm_80-era ops: valid on target sm_103) --------------
__device__ __forceinline__ uint32_t s2u(const void* p) {
    uint32_t a;
    asm("{ .reg .u64 t; cvta.to.shared.u64 t, %1; cvt.u32.u64 %0, t; }" : "=r"(a) : "l"(p));
    return a;
}
__device__ __forceinline__ void cp16(uint32_t saddr, const void* gaddr) {
    asm volatile("cp.async.cg.shared.global [%0], [%1], 16;" :: "r"(saddr), "l"(gaddr));
}
__device__ __forceinline__ void cp_commit() { asm volatile("cp.async.commit_group;"); }
__device__ __forceinline__ void cp_wait2()  { asm volatile("cp.async.wait_group 2;" ::: "memory"); }

__device__ __forceinline__ void ldm4(uint32_t* r, uint32_t addr) {
    asm volatile("ldmatrix.sync.aligned.m8n8.x4.shared.b16 {%0,%1,%2,%3}, [%4];"
                 : "=r"(r[0]), "=r"(r[1]), "=r"(r[2]), "=r"(r[3]) : "r"(addr));
}
__device__ __forceinline__ void mma16816(float* c, const uint32_t* a, const uint32_t* b) {
    asm volatile(
        "mma.sync.aligned.m16n8k16.row.col.f32.bf16.bf16.f32 "
        "{%0,%1,%2,%3}, {%4,%5,%6,%7}, {%8,%9}, {%0,%1,%2,%3};"
        : "+f"(c[0]), "+f"(c[1]), "+f"(c[2]), "+f"(c[3])
        : "r"(a[0]), "r"(a[1]), "r"(a[2]), "r"(a[3]), "r"(b[0]), "r"(b[1]));
}
__device__ __forceinline__ uint32_t pk2(float a, float b) {
    __nv_bfloat162 t = __floats2bfloat162_rn(a, b);
    return *reinterpret_cast<uint32_t*>(&t);
}

// ============================================================================
// Tensor-core GEMM: C[M,N] = scale*((Ahi+Alo)[M,K] @ ((Bhi+Blo)[N,K])^T)+bias
//   3-term split product: Ahi*Bhi + Ahi*Blo + Alo*Bhi (fp32 accum).
//   OUTMODE 0: fp32 out (Cf).  OUTMODE 1: bf16 split out (Ch, Cl).
//   CAUSAL: skip 128x128 tiles strictly above diagonal.
//   PVLIM : K truncated at causal boundary (nchunk = (m0+128)/64).
//   REVY  : reverse blockIdx.y mapping (heavy CTAs launch first for PVLIM).
// ============================================================================
template<int OUTMODE, bool HAS_BIAS, bool CAUSAL, bool PVLIM, bool REVY>
__global__ __launch_bounds__(256, 1)
void tc_gemm(const bf16* __restrict__ Ah, const bf16* __restrict__ Al,
             const bf16* __restrict__ Bh, const bf16* __restrict__ Bl,
             const float* __restrict__ bias,
             float* __restrict__ Cf, bf16* __restrict__ Ch, bf16* __restrict__ Cl,
             int Kfull, int ldA, int ldB, int ldC, float scale,
             size_t sA, size_t sB, size_t sC)
{
    const int bmi = REVY ? (gridDim.y - 1 - blockIdx.y) : blockIdx.y;
    const int m0 = bmi * TM;
    const int n0 = blockIdx.x * TN;
    if (CAUSAL && n0 > m0) return;

    const int z = blockIdx.z;
    Ah += (size_t)z * sA;  Al += (size_t)z * sA;
    Bh += (size_t)z * sB;  Bl += (size_t)z * sB;

    extern __shared__ char dsm[];
    const uint32_t smem = s2u(dsm);

    const int tid  = threadIdx.x;
    const int wid  = tid >> 5;
    const int lane = tid & 31;
    const int wm   = wid & 3;    // 4 warp-rows  (32 M each)
    const int wn   = wid >> 2;   // 2 warp-cols  (64 N each)

    const int nchunk = PVLIM ? (m0 + TM) / BK : Kfull / BK;

    // ---- loader: each thread = half a row (4x16B segs) of each tile ---------
    const int lrow = tid >> 1;            // 0..127
    const int sb   = (tid & 1) * 4;       // seg base 0 or 4
    const char* gp[4];
    uint32_t    so[4][4];
    {
        const bf16* bases[4] = {Ah, Al, Bh, Bl};
        #pragma unroll
        for (int t = 0; t < 4; t++) {
            const int off = (t < 2) ? m0 : n0;
            const int ld  = (t < 2) ? ldA : ldB;
            gp[t] = (const char*)(bases[t] + (size_t)(off + lrow) * ld);
            #pragma unroll
            for (int j = 0; j < 4; j++) {
                const int seg = sb + j;
                so[t][j] = (uint32_t)(t * TILE_BYTES + lrow * 128 +
                                      ((seg ^ (lrow & 7)) << 4));
            }
        }
    }

    auto load_stage = [&](int slot, int chunk) {
        if (chunk < nchunk) {
            const uint32_t s0 = smem + slot * STAGE_BYTES;
            const size_t goff = (size_t)chunk * 128;    // 64 bf16 = 128 bytes
            #pragma unroll
            for (int t = 0; t < 4; t++) {
                #pragma unroll
                for (int j = 0; j < 4; j++)
                    cp16(s0 + so[t][j], gp[t] + goff + (size_t)(sb + j) * 16);
            }
        }
        cp_commit();
    };

    float acc[2][8][4];
    #pragma unroll
    for (int a = 0; a < 2; a++)
        #pragma unroll
        for (int b = 0; b < 8; b++)
            #pragma unroll
            for (int c = 0; c < 4; c++) acc[a][b][c] = 0.f;

    load_stage(0, 0);
    load_stage(1, 1);
    load_stage(2, 2);

    // fragment address components (constant per thread)
    const int a_r  = lane & 15;
    const int a_kh = lane >> 4;
    const int b_nl = ((lane >> 4) & 1) * 8 + (lane & 7);
    const int b_kh = (lane >> 3) & 1;

    for (int i = 0; i < nchunk; i++) {
        cp_wait2();
        __syncthreads();
        const uint32_t s0 = smem + (i % 3) * STAGE_BYTES;

        #pragma unroll
        for (int kk = 0; kk < 4; kk++) {
            uint32_t ahf[2][4], alf[2][4], bhf[4][4], blf[4][4];
            #pragma unroll
            for (int mt = 0; mt < 2; mt++) {
                const int row = wm * 32 + mt * 16 + a_r;
                const int seg = kk * 2 + a_kh;
                const uint32_t off = (uint32_t)(row * 128 + ((seg ^ (row & 7)) << 4));
                ldm4(ahf[mt], s0 + 0 * TILE_BYTES + off);
                ldm4(alf[mt], s0 + 1 * TILE_BYTES + off);
            }
            #pragma unroll
            for (int p = 0; p < 4; p++) {
                const int row = wn * 64 + p * 16 + b_nl;
                const int seg = kk * 2 + b_kh;
                const uint32_t off = (uint32_t)(row * 128 + ((seg ^ (row & 7)) << 4));
                ldm4(bhf[p], s0 + 2 * TILE_BYTES + off);
                ldm4(blf[p], s0 + 3 * TILE_BYTES + off);
            }
            #pragma unroll
            for (int mt = 0; mt < 2; mt++) {
                #pragma unroll
                for (int nt = 0; nt < 8; nt++) {
                    const int p = nt >> 1, o = (nt & 1) * 2;
                    mma16816(acc[mt][nt], ahf[mt], &bhf[p][o]);
                    mma16816(acc[mt][nt], ahf[mt], &blf[p][o]);
                    mma16816(acc[mt][nt], alf[mt], &bhf[p][o]);
                }
            }
        }
        __syncthreads();
        load_stage(i % 3, i + 3);
    }

    // ---- epilogue -------------------------------------------------------------
    #pragma unroll
    for (int mt = 0; mt < 2; mt++) {
        #pragma unroll
        for (int h = 0; h < 2; h++) {
            const int row = m0 + wm * 32 + mt * 16 + (lane >> 2) + 8 * h;
            #pragma unroll
            for (int nt = 0; nt < 8; nt++) {
                const int col = n0 + wn * 64 + nt * 8 + (lane & 3) * 2;
                float v0 = acc[mt][nt][2 * h + 0] * scale;
                float v1 = acc[mt][nt][2 * h + 1] * scale;
                if (HAS_BIAS) {
                    const float2 bb = *reinterpret_cast<const float2*>(bias + col);
                    v0 += bb.x; v1 += bb.y;
                }
                if (OUTMODE == 0) {
                    *reinterpret_cast<float2*>(
                        Cf + (size_t)z * sC + (size_t)row * ldC + col) =
                        make_float2(v0, v1);
                } else {
                    float h0 = __bfloat162float(__float2bfloat16(v0));
                    float h1 = __bfloat162float(__float2bfloat16(v1));
                    *reinterpret_cast<uint32_t*>(
                        Ch + (size_t)z * sC + (size_t)row * ldC + col) = pk2(h0, h1);
                    *reinterpret_cast<uint32_t*>(
                        Cl + (size_t)z * sC + (size_t)row * ldC + col) =
                        pk2(v0 - h0, v1 - h1);
                }
            }
        }
    }
}

// ============================================================================
// prep kernels
// ============================================================================
__global__ void split_kernel(const float* __restrict__ in,
                             bf16* __restrict__ oh, bf16* __restrict__ ol, int n)
{
    int i = blockIdx.x * blockDim.x + threadIdx.x;
    if (i >= n) return;
    float v = in[i];
    bf16 h = __float2bfloat16(v);
    oh[i] = h;
    ol[i] = __float2bfloat16(v - __bfloat162float(h));
}

// transpose + split: in [R,C] fp32 -> out hi/lo [C,R] bf16
__global__ void tsplit_kernel(const float* __restrict__ in,
                              bf16* __restrict__ oh, bf16* __restrict__ ol,
                              int R, int C)
{
    __shared__ float t[32][33];
    const int c0 = blockIdx.x * 32, r0 = blockIdx.y * 32;
    const int tx = threadIdx.x, ty = threadIdx.y;
    #pragma unroll
    for (int k = 0; k < 4; k++)
        t[ty + 8 * k][tx] = in[(size_t)(r0 + ty + 8 * k) * C + c0 + tx];
    __syncthreads();
    #pragma unroll
    for (int k = 0; k < 4; k++) {
        float v = t[tx][ty + 8 * k];
        bf16 h = __float2bfloat16(v);
        size_t o = (size_t)(c0 + ty + 8 * k) * R + r0 + tx;
        oh[o] = h;
        ol[o] = __float2bfloat16(v - __bfloat162float(h));
    }
}

// V transpose+split from the combined QKV split output.
// reads v = hi+lo at [z*SEQ+s][2048+d] (ld NQKV) -> vth/vtl [z][d][s]
__global__ void vtsplit_kernel(const bf16* __restrict__ qh, const bf16* __restrict__ ql,
                               bf16* __restrict__ oh, bf16* __restrict__ ol)
{
    __shared__ float t[32][33];
    const int z = blockIdx.z;
    const int d0 = blockIdx.x * 32, s0 = blockIdx.y * 32;
    const int tx = threadIdx.x, ty = threadIdx.y;
    #pragma unroll
    for (int k = 0; k < 4; k++) {
        size_t idx = (size_t)(z * SEQ + s0 + ty + 8 * k) * NQKV + 2 * DM + d0 + tx;
        t[ty + 8 * k][tx] = __bfloat162float(qh[idx]) + __bfloat162float(ql[idx]);
    }
    __syncthreads();
    #pragma unroll
    for (int k = 0; k < 4; k++) {
        float v = t[tx][ty + 8 * k];
        bf16 h = __float2bfloat16(v);
        size_t o = (size_t)z * DM * SEQ + (size_t)(d0 + ty + 8 * k) * SEQ + s0 + tx;
        oh[o] = h;
        ol[o] = __float2bfloat16(v - __bfloat162float(h));
    }
}

__global__ void bias_concat_kernel(const float* a, const float* b, const float* c,
                                   float* o)
{
    int i = blockIdx.x * blockDim.x + threadIdx.x;
    if (i >= NQKV) return;
    o[i] = (i < DM) ? a[i] : (i < 2 * DM ? b[i - DM] : c[i - 2 * DM]);
}

// causal softmax: fp32 scores -> split bf16 weights, zero-fill to 128 boundary
__global__ __launch_bounds__(256)
void softmax_split_kernel(float* __restrict__ P,
                          bf16* __restrict__ Ph, bf16* __restrict__ Pl)
{
    const int rowi = blockIdx.x;
    const int b = rowi / SEQ, q = rowi % SEQ;
    const size_t off = (size_t)b * SEQ * SEQ + (size_t)q * SEQ;
    float* p = P + off;
    bf16* ph = Ph + off;
    bf16* pl = Pl + off;
    const int n = q + 1;

    __shared__ float red[256];
    const int tid = threadIdx.x;

    float mx = -CUDART_INF_F;
    for (int k = tid; k < n; k += 256) mx = fmaxf(mx, p[k]);
    red[tid] = mx; __syncthreads();
    #pragma unroll
    for (int s = 128; s > 0; s >>= 1) {
        if (tid < s) red[tid] = fmaxf(red[tid], red[tid + s]);
        __syncthreads();
    }
    mx = red[0]; __syncthreads();

    float sum = 0.f;
    for (int k = tid; k < n; k += 256) {
        float e = expf(p[k] - mx);
        p[k] = e;
        sum += e;
    }
    red[tid] = sum; __syncthreads();
    #pragma unroll
    for (int s = 128; s > 0; s >>= 1) {
        if (tid < s) red[tid] += red[tid + s];
        __syncthreads();
    }
    const float inv = 1.f / red[0];

    for (int k = tid; k < n; k += 256) {
        float w = p[k] * inv;
        bf16 h = __float2bfloat16(w);
        ph[k] = h;
        pl[k] = __float2bfloat16(w - __bfloat162float(h));
    }
    const int fillEnd = ((q >> 7) + 1) << 7;
    for (int k = n + tid; k < fillEnd; k += 256) {
        ph[k] = __float2bfloat16(0.f);
        pl[k] = __float2bfloat16(0.f);
    }
}

// ============================================================================
extern "C" void kernel_launch(void* const* d_in, const int*, int, void* d_out, int)
{
    const float* x  = (const float*)d_in[0];
    const float* Wq = (const float*)d_in[1];
    const float* bq = (const float*)d_in[2];
    const float* Wk = (const float*)d_in[3];
    const float* bk = (const float*)d_in[4];
    const float* Wv = (const float*)d_in[5];
    const float* bv = (const float*)d_in[6];
    const float* Wo = (const float*)d_in[7];
    const float* bo = (const float*)d_in[8];
    float* out = (float*)d_out;

    bf16 *xh, *xl, *wh, *wl, *woh, *wol, *qkvh, *qkvl, *vth, *vtl, *phh, *pll, *aoh, *aol;
    float *p, *bqkv;
    cudaGetSymbolAddress((void**)&xh,   g_xh);   cudaGetSymbolAddress((void**)&xl,   g_xl);
    cudaGetSymbolAddress((void**)&wh,   g_wh);   cudaGetSymbolAddress((void**)&wl,   g_wl);
    cudaGetSymbolAddress((void**)&bqkv, g_bqkv);
    cudaGetSymbolAddress((void**)&woh,  g_woh);  cudaGetSymbolAddress((void**)&wol,  g_wol);
    cudaGetSymbolAddress((void**)&qkvh, g_qkvh); cudaGetSymbolAddress((void**)&qkvl, g_qkvl);
    cudaGetSymbolAddress((void**)&vth,  g_vth);  cudaGetSymbolAddress((void**)&vtl,  g_vtl);
    cudaGetSymbolAddress((void**)&p,    g_p);
    cudaGetSymbolAddress((void**)&phh,  g_ph);   cudaGetSymbolAddress((void**)&pll,  g_pl);
    cudaGetSymbolAddress((void**)&aoh,  g_aoh);  cudaGetSymbolAddress((void**)&aol,  g_aol);

    cudaFuncSetAttribute(tc_gemm<1, true,  false, false, false>, cudaFuncAttributeMaxDynamicSharedMemorySize, SMEM_DYN);
    cudaFuncSetAttribute(tc_gemm<0, false, true,  false, false>, cudaFuncAttributeMaxDynamicSharedMemorySize, SMEM_DYN);
    cudaFuncSetAttribute(tc_gemm<1, false, false, true,  true >, cudaFuncAttributeMaxDynamicSharedMemorySize, SMEM_DYN);
    cudaFuncSetAttribute(tc_gemm<0, true,  false, false, false>, cudaFuncAttributeMaxDynamicSharedMemorySize, SMEM_DYN);

    // ---- prep: split x, transpose+split weights (Wqkv concatenated) ----------
    split_kernel<<<(MROWS * DM + 255) / 256, 256>>>(x, xh, xl, MROWS * DM);
    {
        dim3 blk(32, 8), grid(DM / 32, DM / 32);
        tsplit_kernel<<<grid, blk>>>(Wq, wh,               wl,               DM, DM);
        tsplit_kernel<<<grid, blk>>>(Wk, wh + DM * DM,     wl + DM * DM,     DM, DM);
        tsplit_kernel<<<grid, blk>>>(Wv, wh + 2 * DM * DM, wl + 2 * DM * DM, DM, DM);
        tsplit_kernel<<<grid, blk>>>(Wo, woh,              wol,              DM, DM);
    }
    bias_concat_kernel<<<(NQKV + 255) / 256, 256>>>(bq, bk, bv, bqkv);

    // ---- fused QKV projection: [8192,1024] @ [1024,3072] + b (one launch) ----
    {
        dim3 grid(NQKV / TN, MROWS / TM, 1), blk(256);
        tc_gemm<1, true, false, false, false><<<grid, blk, SMEM_DYN>>>(
            xh, xl, wh, wl, bqkv, nullptr, qkvh, qkvl,
            DM, DM, DM, NQKV, 1.f, 0, 0, 0);
    }

    // ---- V transpose+split ----------------------------------------------------
    {
        dim3 blk(32, 8), grid(DM / 32, SEQ / 32, BATCH);
        vtsplit_kernel<<<grid, blk>>>(qkvh, qkvl, vth, vtl);
    }

    // ---- scores = Q @ K^T / 8 (causal tile skip); Q,K read from qkv ld=3072 --
    {
        dim3 grid(SEQ / TN, SEQ / TM, BATCH), blk(256);
        tc_gemm<0, false, true, false, false><<<grid, blk, SMEM_DYN>>>(
            qkvh, qkvl, qkvh + DM, qkvl + DM, nullptr, p, nullptr, nullptr,
            DM, NQKV, NQKV, SEQ, 0.125f,
            (size_t)SEQ * NQKV, (size_t)SEQ * NQKV, (size_t)SEQ * SEQ);
    }

    // ---- softmax ----------------------------------------------------------------
    softmax_split_kernel<<<MROWS, 256>>>(p, phh, pll);

    // ---- attn_out = P @ V (K truncated at causal boundary, heavy CTAs first) --
    {
        dim3 grid(DM / TN, SEQ / TM, BATCH), blk(256);
        tc_gemm<1, false, false, true, true><<<grid, blk, SMEM_DYN>>>(
            phh, pll, vth, vtl, nullptr, nullptr, aoh, aol,
            SEQ, SEQ, SEQ, DM, 1.f,
            (size_t)SEQ * SEQ, (size_t)DM * SEQ, (size_t)SEQ * DM);
    }

    // ---- out = attn_out @ Wo + bo ------------------------------------------------
    {
        dim3 grid(DM / TN, MROWS / TM, 1), blk(256);
        tc_gemm<0, true, false, false, false><<<grid, blk, SMEM_DYN>>>(
            aoh, aol, woh, wol, bo, out, nullptr, nullptr,
            DM, DM, DM, DM, 1.f, 0, 0, 0);
    }
}

// round 7
// speedup vs baseline: 1.2757x; 1.0007x over previous
#include <cuda_runtime.h>
#include <cuda_bf16.h>
#include <math_constants.h>
#include <stdint.h>

#define BATCH 4
#define SEQ   2048
#define DM    1024
#define MROWS (BATCH * SEQ)
#define NQKV  (3 * DM)                // 3072

// ---- GEMM tiling -------------------------------------------------------------
#define TM 128
#define TN 128
#define BK 64                         // bf16 elems per K-chunk (128 bytes/row)
#define TILE_BYTES (128 * 128)        // 16 KB per operand tile
#define STAGE_BYTES (4 * TILE_BYTES)  // Ahi,Alo,Bhi,Blo = 64 KB
#define NSTAGE 3
#define SMEM_DYN (NSTAGE * STAGE_BYTES)   // 192 KB

typedef __nv_bfloat16 bf16;

// ---- scratch (static __device__: allocation-free) ------------------------------
#define AL1K __align__(1024)
__device__ AL1K bf16  g_xh  [MROWS * DM];
__device__ AL1K bf16  g_xl  [MROWS * DM];
__device__ AL1K bf16  g_wh  [NQKV * DM];              // [Wq^T;Wk^T;Wv^T] hi
__device__ AL1K bf16  g_wl  [NQKV * DM];
__device__ AL1K float g_bqkv[NQKV];
__device__ AL1K bf16  g_woh [DM * DM];
__device__ AL1K bf16  g_wol [DM * DM];
__device__ AL1K bf16  g_qkvh[(size_t)MROWS * NQKV];   // [B*S][3D]
__device__ AL1K bf16  g_qkvl[(size_t)MROWS * NQKV];
__device__ AL1K bf16  g_vth [MROWS * DM];             // [B][D][S]
__device__ AL1K bf16  g_vtl [MROWS * DM];
__device__ AL1K float g_p   [(size_t)BATCH * SEQ * SEQ];
__device__ AL1K bf16  g_ph  [(size_t)BATCH * SEQ * SEQ];
__device__ AL1K bf16  g_pl  [(size_t)BATCH * SEQ * SEQ];
__device__ AL1K bf16  g_aoh [MROWS * DM];
__device__ AL1K bf16  g_aol [MROWS * DM];

// ---- PTX helpers ---------------------------------------------------------------
__device__ __forceinline__ uint32_t s2u(const void* p) {
    uint32_t a;
    asm("{ .reg .u64 t; cvta.to.shared.u64 t, %1; cvt.u32.u64 %0, t; }" : "=r"(a) : "l"(p));
    return a;
}
__device__ __forceinline__ void cp16(uint32_t saddr, const void* gaddr) {
    asm volatile("cp.async.cg.shared.global [%0], [%1], 16;" :: "r"(saddr), "l"(gaddr));
}
__device__ __forceinline__ void cp_commit() { asm volatile("cp.async.commit_group;"); }
__device__ __forceinline__ void cp_wait2()  { asm volatile("cp.async.wait_group 2;" ::: "memory"); }

__device__ __forceinline__ void ldm4(uint32_t* r, uint32_t addr) {
    asm volatile("ldmatrix.sync.aligned.m8n8.x4.shared.b16 {%0,%1,%2,%3}, [%4];"
                 : "=r"(r[0]), "=r"(r[1]), "=r"(r[2]), "=r"(r[3]) : "r"(addr));
}
__device__ __forceinline__ void mma16816(float* c, const uint32_t* a, const uint32_t* b) {
    asm volatile(
        "mma.sync.aligned.m16n8k16.row.col.f32.bf16.bf16.f32 "
        "{%0,%1,%2,%3}, {%4,%5,%6,%7}, {%8,%9}, {%0,%1,%2,%3};"
        : "+f"(c[0]), "+f"(c[1]), "+f"(c[2]), "+f"(c[3])
        : "r"(a[0]), "r"(a[1]), "r"(a[2]), "r"(a[3]), "r"(b[0]), "r"(b[1]));
}
__device__ __forceinline__ uint32_t pk2(float a, float b) {
    __nv_bfloat162 t = __floats2bfloat162_rn(a, b);
    return *reinterpret_cast<uint32_t*>(&t);
}

// ============================================================================
// Tensor-core GEMM: C[M,N] = scale*((Ahi+Alo)[M,K] @ ((Bhi+Blo)[N,K])^T)+bias
//   3-term split product, TERM-MAJOR issue order (no RAW chains on accs).
//   OUTMODE 0: fp32 out (Cf).  OUTMODE 1: bf16 split out (Ch, Cl).
//   CAUSAL: skip 128x128 tiles strictly above diagonal.
//   PVLIM : K truncated at causal boundary (nchunk = (m0+128)/64).
//   REVY  : reverse blockIdx.y mapping (heavy CTAs launch first).
// ============================================================================
template<int OUTMODE, bool HAS_BIAS, bool CAUSAL, bool PVLIM, bool REVY>
__global__ __launch_bounds__(256, 1)
void tc_gemm(const bf16* __restrict__ Ah, const bf16* __restrict__ Al,
             const bf16* __restrict__ Bh, const bf16* __restrict__ Bl,
             const float* __restrict__ bias,
             float* __restrict__ Cf, bf16* __restrict__ Ch, bf16* __restrict__ Cl,
             int Kfull, int ldA, int ldB, int ldC, float scale,
             size_t sA, size_t sB, size_t sC)
{
    const int bmi = REVY ? (gridDim.y - 1 - blockIdx.y) : blockIdx.y;
    const int m0 = bmi * TM;
    const int n0 = blockIdx.x * TN;
    if (CAUSAL && n0 > m0) return;

    const int z = blockIdx.z;
    Ah += (size_t)z * sA;  Al += (size_t)z * sA;
    Bh += (size_t)z * sB;  Bl += (size_t)z * sB;

    extern __shared__ char dsm[];
    const uint32_t smem = s2u(dsm);

    const int tid  = threadIdx.x;
    const int wid  = tid >> 5;
    const int lane = tid & 31;
    const int wm   = wid & 3;    // 4 warp-rows  (32 M each)
    const int wn   = wid >> 2;   // 2 warp-cols  (64 N each)

    const int nchunk = PVLIM ? (m0 + TM) / BK : Kfull / BK;

    // ---- loader: each thread = half a row (4x16B segs) of each tile -----------
    const int lrow = tid >> 1;            // 0..127
    const int sb   = (tid & 1) * 4;       // seg base 0 or 4
    const char* gp[4];
    uint32_t    so[4][4];
    {
        const bf16* bases[4] = {Ah, Al, Bh, Bl};
        #pragma unroll
        for (int t = 0; t < 4; t++) {
            const int off = (t < 2) ? m0 : n0;
            const int ld  = (t < 2) ? ldA : ldB;
            gp[t] = (const char*)(bases[t] + (size_t)(off + lrow) * ld);
            #pragma unroll
            for (int j = 0; j < 4; j++) {
                const int seg = sb + j;
                so[t][j] = (uint32_t)(t * TILE_BYTES + lrow * 128 +
                                      ((seg ^ (lrow & 7)) << 4));
            }
        }
    }

    auto load_stage = [&](int slot, int chunk) {
        if (chunk < nchunk) {
            const uint32_t s0 = smem + slot * STAGE_BYTES;
            const size_t goff = (size_t)chunk * 128;    // 64 bf16 = 128 bytes
            #pragma unroll
            for (int t = 0; t < 4; t++) {
                #pragma unroll
                for (int j = 0; j < 4; j++)
                    cp16(s0 + so[t][j], gp[t] + goff + (size_t)(sb + j) * 16);
            }
        }
        cp_commit();
    };

    float acc[2][8][4];
    #pragma unroll
    for (int a = 0; a < 2; a++)
        #pragma unroll
        for (int b = 0; b < 8; b++)
            #pragma unroll
            for (int c = 0; c < 4; c++) acc[a][b][c] = 0.f;

    load_stage(0, 0);
    load_stage(1, 1);
    load_stage(2, 2);

    // fragment address components (constant per thread)
    const int a_r  = lane & 15;
    const int a_kh = lane >> 4;
    const int b_nl = ((lane >> 4) & 1) * 8 + (lane & 7);
    const int b_kh = (lane >> 3) & 1;

    for (int i = 0; i < nchunk; i++) {
        cp_wait2();
        __syncthreads();
        const uint32_t s0 = smem + (i % 3) * STAGE_BYTES;

        #pragma unroll
        for (int kk = 0; kk < 4; kk++) {
            uint32_t ahf[2][4], alf[2][4], bhf[4][4], blf[4][4];
            #pragma unroll
            for (int mt = 0; mt < 2; mt++) {
                const int row = wm * 32 + mt * 16 + a_r;
                const int seg = kk * 2 + a_kh;
                const uint32_t off = (uint32_t)(row * 128 + ((seg ^ (row & 7)) << 4));
                ldm4(ahf[mt], s0 + 0 * TILE_BYTES + off);
                ldm4(alf[mt], s0 + 1 * TILE_BYTES + off);
            }
            #pragma unroll
            for (int p = 0; p < 4; p++) {
                const int row = wn * 64 + p * 16 + b_nl;
                const int seg = kk * 2 + b_kh;
                const uint32_t off = (uint32_t)(row * 128 + ((seg ^ (row & 7)) << 4));
                ldm4(bhf[p], s0 + 2 * TILE_BYTES + off);
                ldm4(blf[p], s0 + 3 * TILE_BYTES + off);
            }
            // TERM-MAJOR: 16 independent accumulators between same-acc reuses.
            #pragma unroll
            for (int mt = 0; mt < 2; mt++)
                #pragma unroll
                for (int nt = 0; nt < 8; nt++)
                    mma16816(acc[mt][nt], ahf[mt], &bhf[nt >> 1][(nt & 1) * 2]);
            #pragma unroll
            for (int mt = 0; mt < 2; mt++)
                #pragma unroll
                for (int nt = 0; nt < 8; nt++)
                    mma16816(acc[mt][nt], ahf[mt], &blf[nt >> 1][(nt & 1) * 2]);
            #pragma unroll
            for (int mt = 0; mt < 2; mt++)
                #pragma unroll
                for (int nt = 0; nt < 8; nt++)
                    mma16816(acc[mt][nt], alf[mt], &bhf[nt >> 1][(nt & 1) * 2]);
        }
        __syncthreads();
        load_stage(i % 3, i + 3);
    }

    // ---- epilogue ---------------------------------------------------------------
    #pragma unroll
    for (int mt = 0; mt < 2; mt++) {
        #pragma unroll
        for (int h = 0; h < 2; h++) {
            const int row = m0 + wm * 32 + mt * 16 + (lane >> 2) + 8 * h;
            #pragma unroll
            for (int nt = 0; nt < 8; nt++) {
                const int col = n0 + wn * 64 + nt * 8 + (lane & 3) * 2;
                float v0 = acc[mt][nt][2 * h + 0] * scale;
                float v1 = acc[mt][nt][2 * h + 1] * scale;
                if (HAS_BIAS) {
                    const float2 bb = *reinterpret_cast<const float2*>(bias + col);
                    v0 += bb.x; v1 += bb.y;
                }
                if (OUTMODE == 0) {
                    *reinterpret_cast<float2*>(
                        Cf + (size_t)z * sC + (size_t)row * ldC + col) =
                        make_float2(v0, v1);
                } else {
                    float h0 = __bfloat162float(__float2bfloat16(v0));
                    float h1 = __bfloat162float(__float2bfloat16(v1));
                    *reinterpret_cast<uint32_t*>(
                        Ch + (size_t)z * sC + (size_t)row * ldC + col) = pk2(h0, h1);
                    *reinterpret_cast<uint32_t*>(
                        Cl + (size_t)z * sC + (size_t)row * ldC + col) =
                        pk2(v0 - h0, v1 - h1);
                }
            }
        }
    }
}

// ============================================================================
// prep kernels
// ============================================================================
__global__ void split_kernel(const float* __restrict__ in,
                             bf16* __restrict__ oh, bf16* __restrict__ ol, int n)
{
    int i = blockIdx.x * blockDim.x + threadIdx.x;
    if (i >= n) return;
    float v = in[i];
    bf16 h = __float2bfloat16(v);
    oh[i] = h;
    ol[i] = __float2bfloat16(v - __bfloat162float(h));
}

// transpose + split: in [R,C] fp32 -> out hi/lo [C,R] bf16
__global__ void tsplit_kernel(const float* __restrict__ in,
                              bf16* __restrict__ oh, bf16* __restrict__ ol,
                              int R, int C)
{
    __shared__ float t[32][33];
    const int c0 = blockIdx.x * 32, r0 = blockIdx.y * 32;
    const int tx = threadIdx.x, ty = threadIdx.y;
    #pragma unroll
    for (int k = 0; k < 4; k++)
        t[ty + 8 * k][tx] = in[(size_t)(r0 + ty + 8 * k) * C + c0 + tx];
    __syncthreads();
    #pragma unroll
    for (int k = 0; k < 4; k++) {
        float v = t[tx][ty + 8 * k];
        bf16 h = __float2bfloat16(v);
        size_t o = (size_t)(c0 + ty + 8 * k) * R + r0 + tx;
        oh[o] = h;
        ol[o] = __float2bfloat16(v - __bfloat162float(h));
    }
}

// V transpose+split from the combined QKV split output.
__global__ void vtsplit_kernel(const bf16* __restrict__ qh, const bf16* __restrict__ ql,
                               bf16* __restrict__ oh, bf16* __restrict__ ol)
{
    __shared__ float t[32][33];
    const int z = blockIdx.z;
    const int d0 = blockIdx.x * 32, s0 = blockIdx.y * 32;
    const int tx = threadIdx.x, ty = threadIdx.y;
    #pragma unroll
    for (int k = 0; k < 4; k++) {
        size_t idx = (size_t)(z * SEQ + s0 + ty + 8 * k) * NQKV + 2 * DM + d0 + tx;
        t[ty + 8 * k][tx] = __bfloat162float(qh[idx]) + __bfloat162float(ql[idx]);
    }
    __syncthreads();
    #pragma unroll
    for (int k = 0; k < 4; k++) {
        float v = t[tx][ty + 8 * k];
        bf16 h = __float2bfloat16(v);
        size_t o = (size_t)z * DM * SEQ + (size_t)(d0 + ty + 8 * k) * SEQ + s0 + tx;
        oh[o] = h;
        ol[o] = __float2bfloat16(v - __bfloat162float(h));
    }
}

__global__ void bias_concat_kernel(const float* a, const float* b, const float* c,
                                   float* o)
{
    int i = blockIdx.x * blockDim.x + threadIdx.x;
    if (i >= NQKV) return;
    o[i] = (i < DM) ? a[i] : (i < 2 * DM ? b[i - DM] : c[i - 2 * DM]);
}

// causal softmax: fp32 scores -> split bf16 weights, zero-fill to 128 boundary
__global__ __launch_bounds__(256)
void softmax_split_kernel(float* __restrict__ P,
                          bf16* __restrict__ Ph, bf16* __restrict__ Pl)
{
    const int rowi = blockIdx.x;
    const int b = rowi / SEQ, q = rowi % SEQ;
    const size_t off = (size_t)b * SEQ * SEQ + (size_t)q * SEQ;
    float* p = P + off;
    bf16* ph = Ph + off;
    bf16* pl = Pl + off;
    const int n = q + 1;

    __shared__ float red[256];
    const int tid = threadIdx.x;

    float mx = -CUDART_INF_F;
    for (int k = tid; k < n; k += 256) mx = fmaxf(mx, p[k]);
    red[tid] = mx; __syncthreads();
    #pragma unroll
    for (int s = 128; s > 0; s >>= 1) {
        if (tid < s) red[tid] = fmaxf(red[tid], red[tid + s]);
        __syncthreads();
    }
    mx = red[0]; __syncthreads();

    float sum = 0.f;
    for (int k = tid; k < n; k += 256) {
        float e = expf(p[k] - mx);
        p[k] = e;
        sum += e;
    }
    red[tid] = sum; __syncthreads();
    #pragma unroll
    for (int s = 128; s > 0; s >>= 1) {
        if (tid < s) red[tid] += red[tid + s];
        __syncthreads();
    }
    const float inv = 1.f / red[0];

    for (int k = tid; k < n; k += 256) {
        float w = p[k] * inv;
        bf16 h = __float2bfloat16(w);
        ph[k] = h;
        pl[k] = __float2bfloat16(w - __bfloat162float(h));
    }
    const int fillEnd = ((q >> 7) + 1) << 7;
    for (int k = n + tid; k < fillEnd; k += 256) {
        ph[k] = __float2bfloat16(0.f);
        pl[k] = __float2bfloat16(0.f);
    }
}

// ============================================================================
extern "C" void kernel_launch(void* const* d_in, const int*, int, void* d_out, int)
{
    const float* x  = (const float*)d_in[0];
    const float* Wq = (const float*)d_in[1];
    const float* bq = (const float*)d_in[2];
    const float* Wk = (const float*)d_in[3];
    const float* bk = (const float*)d_in[4];
    const float* Wv = (const float*)d_in[5];
    const float* bv = (const float*)d_in[6];
    const float* Wo = (const float*)d_in[7];
    const float* bo = (const float*)d_in[8];
    float* out = (float*)d_out;

    bf16 *xh, *xl, *wh, *wl, *woh, *wol, *qkvh, *qkvl, *vth, *vtl, *phh, *pll, *aoh, *aol;
    float *p, *bqkv;
    cudaGetSymbolAddress((void**)&xh,   g_xh);   cudaGetSymbolAddress((void**)&xl,   g_xl);
    cudaGetSymbolAddress((void**)&wh,   g_wh);   cudaGetSymbolAddress((void**)&wl,   g_wl);
    cudaGetSymbolAddress((void**)&bqkv, g_bqkv);
    cudaGetSymbolAddress((void**)&woh,  g_woh);  cudaGetSymbolAddress((void**)&wol,  g_wol);
    cudaGetSymbolAddress((void**)&qkvh, g_qkvh); cudaGetSymbolAddress((void**)&qkvl, g_qkvl);
    cudaGetSymbolAddress((void**)&vth,  g_vth);  cudaGetSymbolAddress((void**)&vtl,  g_vtl);
    cudaGetSymbolAddress((void**)&p,    g_p);
    cudaGetSymbolAddress((void**)&phh,  g_ph);   cudaGetSymbolAddress((void**)&pll,  g_pl);
    cudaGetSymbolAddress((void**)&aoh,  g_aoh);  cudaGetSymbolAddress((void**)&aol,  g_aol);

    cudaFuncSetAttribute(tc_gemm<1, true,  false, false, false>, cudaFuncAttributeMaxDynamicSharedMemorySize, SMEM_DYN);
    cudaFuncSetAttribute(tc_gemm<0, false, true,  false, false>, cudaFuncAttributeMaxDynamicSharedMemorySize, SMEM_DYN);
    cudaFuncSetAttribute(tc_gemm<1, false, false, true,  true >, cudaFuncAttributeMaxDynamicSharedMemorySize, SMEM_DYN);
    cudaFuncSetAttribute(tc_gemm<0, true,  false, false, false>, cudaFuncAttributeMaxDynamicSharedMemorySize, SMEM_DYN);

    // ---- prep: split x, transpose+split weights (Wqkv concatenated) ------------
    split_kernel<<<(MROWS * DM + 255) / 256, 256>>>(x, xh, xl, MROWS * DM);
    {
        dim3 blk(32, 8), grid(DM / 32, DM / 32);
        tsplit_kernel<<<grid, blk>>>(Wq, wh,               wl,               DM, DM);
        tsplit_kernel<<<grid, blk>>>(Wk, wh + DM * DM,     wl + DM * DM,     DM, DM);
        tsplit_kernel<<<grid, blk>>>(Wv, wh + 2 * DM * DM, wl + 2 * DM * DM, DM, DM);
        tsplit_kernel<<<grid, blk>>>(Wo, woh,              wol,              DM, DM);
    }
    bias_concat_kernel<<<(NQKV + 255) / 256, 256>>>(bq, bk, bv, bqkv);

    // ---- fused QKV projection: [8192,1024] @ [1024,3072] + b -------------------
    {
        dim3 grid(NQKV / TN, MROWS / TM, 1), blk(256);
        tc_gemm<1, true, false, false, false><<<grid, blk, SMEM_DYN>>>(
            xh, xl, wh, wl, bqkv, nullptr, qkvh, qkvl,
            DM, DM, DM, NQKV, 1.f, 0, 0, 0);
    }

    // ---- V transpose+split -------------------------------------------------------
    {
        dim3 blk(32, 8), grid(DM / 32, SEQ / 32, BATCH);
        vtsplit_kernel<<<grid, blk>>>(qkvh, qkvl, vth, vtl);
    }

    // ---- scores = Q @ K^T / 8 (causal tile skip); Q,K from qkv with ld=3072 ----
    {
        dim3 grid(SEQ / TN, SEQ / TM, BATCH), blk(256);
        tc_gemm<0, false, true, false, false><<<grid, blk, SMEM_DYN>>>(
            qkvh, qkvl, qkvh + DM, qkvl + DM, nullptr, p, nullptr, nullptr,
            DM, NQKV, NQKV, SEQ, 0.125f,
            (size_t)SEQ * NQKV, (size_t)SEQ * NQKV, (size_t)SEQ * SEQ);
    }

    // ---- softmax -------------------------------------------------------------------
    softmax_split_kernel<<<MROWS, 256>>>(p, phh, pll);

    // ---- attn_out = P @ V (K truncated at causal boundary, heavy CTAs first) ----
    {
        dim3 grid(DM / TN, SEQ / TM, BATCH), blk(256);
        tc_gemm<1, false, false, true, true><<<grid, blk, SMEM_DYN>>>(
            phh, pll, vth, vtl, nullptr, nullptr, aoh, aol,
            SEQ, SEQ, SEQ, DM, 1.f,
            (size_t)SEQ * SEQ, (size_t)DM * SEQ, (size_t)SEQ * DM);
    }

    // ---- out = attn_out @ Wo + bo ---------------------------------------------------
    {
        dim3 grid(DM / TN, MROWS / TM, 1), blk(256);
        tc_gemm<0, true, false, false, false><<<grid, blk, SMEM_DYN>>>(
            aoh, aol, woh, wol, bo, out, nullptr, nullptr,
            DM, DM, DM, DM, 1.f, 0, 0, 0);
    }
}

// round 8
// speedup vs baseline: 1.6794x; 1.3165x over previous
#include <cuda_runtime.h>
#include <cuda_bf16.h>
#include <math_constants.h>
#include <stdint.h>

#define BATCH 4
#define SEQ   2048
#define DM    1024
#define MROWS (BATCH * SEQ)

// ---- GEMM tiling (proven config) -------------------------------------------
#define TM 128
#define TN 128
#define BK 64                         // bf16 elems per K-chunk (128 bytes/row)
#define TILE_BYTES (128 * 128)        // 16 KB per operand tile
#define STAGE_BYTES (4 * TILE_BYTES)  // Ahi,Alo,Bhi,Blo = 64 KB
#define NSTAGE 3
#define SMEM_DYN (NSTAGE * STAGE_BYTES)   // 192 KB

typedef __nv_bfloat16 bf16;

// ---- scratch (static __device__: allocation-free) ----------------------------
#define AL1K __align__(1024)
__device__ AL1K bf16  g_xh [MROWS * DM];
__device__ AL1K bf16  g_xl [MROWS * DM];
__device__ AL1K bf16  g_wAh[2 * DM * DM];   // [Wk ; Wo^T] split hi
__device__ AL1K bf16  g_wAl[2 * DM * DM];
__device__ AL1K bf16  g_wBh[2 * DM * DM];   // [Wq ; Wv] split hi
__device__ AL1K bf16  g_wBl[2 * DM * DM];
__device__ AL1K bf16  g_gh [2 * DM * DM];   // [GT ; HT] split hi
__device__ AL1K bf16  g_gl [2 * DM * DM];
__device__ AL1K bf16  g_qxh[(size_t)2 * MROWS * DM];  // [QG ; XH] split hi
__device__ AL1K bf16  g_qxl[(size_t)2 * MROWS * DM];
__device__ AL1K bf16  g_xth[MROWS * DM];    // XH^T per batch [B][D][S]
__device__ AL1K bf16  g_xtl[MROWS * DM];
__device__ AL1K float g_p  [(size_t)BATCH * SEQ * SEQ];
__device__ AL1K bf16  g_ph [(size_t)BATCH * SEQ * SEQ];
__device__ AL1K bf16  g_pl [(size_t)BATCH * SEQ * SEQ];
__device__ AL1K float g_w2 [DM];
__device__ AL1K float g_v  [MROWS];
__device__ AL1K float g_rb [DM];

// ---- PTX helpers ---------------------------------------------------------------
__device__ __forceinline__ uint32_t s2u(const void* p) {
    uint32_t a;
    asm("{ .reg .u64 t; cvta.to.shared.u64 t, %1; cvt.u32.u64 %0, t; }" : "=r"(a) : "l"(p));
    return a;
}
__device__ __forceinline__ void cp16(uint32_t saddr, const void* gaddr) {
    asm volatile("cp.async.cg.shared.global [%0], [%1], 16;" :: "r"(saddr), "l"(gaddr));
}
__device__ __forceinline__ void cp_commit() { asm volatile("cp.async.commit_group;"); }
__device__ __forceinline__ void cp_wait2()  { asm volatile("cp.async.wait_group 2;" ::: "memory"); }

__device__ __forceinline__ void ldm4(uint32_t* r, uint32_t addr) {
    asm volatile("ldmatrix.sync.aligned.m8n8.x4.shared.b16 {%0,%1,%2,%3}, [%4];"
                 : "=r"(r[0]), "=r"(r[1]), "=r"(r[2]), "=r"(r[3]) : "r"(addr));
}
__device__ __forceinline__ void mma16816(float* c, const uint32_t* a, const uint32_t* b) {
    asm volatile(
        "mma.sync.aligned.m16n8k16.row.col.f32.bf16.bf16.f32 "
        "{%0,%1,%2,%3}, {%4,%5,%6,%7}, {%8,%9}, {%0,%1,%2,%3};"
        : "+f"(c[0]), "+f"(c[1]), "+f"(c[2]), "+f"(c[3])
        : "r"(a[0]), "r"(a[1]), "r"(a[2]), "r"(a[3]), "r"(b[0]), "r"(b[1]));
}
__device__ __forceinline__ uint32_t pk2(float a, float b) {
    __nv_bfloat162 t = __floats2bfloat162_rn(a, b);
    return *reinterpret_cast<uint32_t*>(&t);
}

// ============================================================================
// Tensor-core GEMM: C[M,N] = scale*((Ahi+Alo)[M,K] @ ((Bhi+Blo)[N,K])^T)+bias
//   3-term split product, term-major issue order.
//   OUTMODE 0: fp32 out (Cf).  OUTMODE 1: bf16 split out (Ch, Cl).
//   CAUSAL: skip 128x128 tiles strictly above diagonal.
//   PVLIM : K truncated at causal boundary (nchunk = (m0+128)/64).
//   REVY  : reverse blockIdx.y mapping (heavy CTAs launch first).
// ============================================================================
template<int OUTMODE, bool HAS_BIAS, bool CAUSAL, bool PVLIM, bool REVY>
__global__ __launch_bounds__(256, 1)
void tc_gemm(const bf16* __restrict__ Ah, const bf16* __restrict__ Al,
             const bf16* __restrict__ Bh, const bf16* __restrict__ Bl,
             const float* __restrict__ bias,
             float* __restrict__ Cf, bf16* __restrict__ Ch, bf16* __restrict__ Cl,
             int Kfull, int ldA, int ldB, int ldC, float scale,
             size_t sA, size_t sB, size_t sC)
{
    const int bmi = REVY ? (gridDim.y - 1 - blockIdx.y) : blockIdx.y;
    const int m0 = bmi * TM;
    const int n0 = blockIdx.x * TN;
    if (CAUSAL && n0 > m0) return;

    const int z = blockIdx.z;
    Ah += (size_t)z * sA;  Al += (size_t)z * sA;
    Bh += (size_t)z * sB;  Bl += (size_t)z * sB;

    extern __shared__ char dsm[];
    const uint32_t smem = s2u(dsm);

    const int tid  = threadIdx.x;
    const int wid  = tid >> 5;
    const int lane = tid & 31;
    const int wm   = wid & 3;    // 4 warp-rows  (32 M each)
    const int wn   = wid >> 2;   // 2 warp-cols  (64 N each)

    const int nchunk = PVLIM ? (m0 + TM) / BK : Kfull / BK;

    const int lrow = tid >> 1;
    const int sb   = (tid & 1) * 4;
    const char* gp[4];
    uint32_t    so[4][4];
    {
        const bf16* bases[4] = {Ah, Al, Bh, Bl};
        #pragma unroll
        for (int t = 0; t < 4; t++) {
            const int off = (t < 2) ? m0 : n0;
            const int ld  = (t < 2) ? ldA : ldB;
            gp[t] = (const char*)(bases[t] + (size_t)(off + lrow) * ld);
            #pragma unroll
            for (int j = 0; j < 4; j++) {
                const int seg = sb + j;
                so[t][j] = (uint32_t)(t * TILE_BYTES + lrow * 128 +
                                      ((seg ^ (lrow & 7)) << 4));
            }
        }
    }

    auto load_stage = [&](int slot, int chunk) {
        if (chunk < nchunk) {
            const uint32_t s0 = smem + slot * STAGE_BYTES;
            const size_t goff = (size_t)chunk * 128;
            #pragma unroll
            for (int t = 0; t < 4; t++) {
                #pragma unroll
                for (int j = 0; j < 4; j++)
                    cp16(s0 + so[t][j], gp[t] + goff + (size_t)(sb + j) * 16);
            }
        }
        cp_commit();
    };

    float acc[2][8][4];
    #pragma unroll
    for (int a = 0; a < 2; a++)
        #pragma unroll
        for (int b = 0; b < 8; b++)
            #pragma unroll
            for (int c = 0; c < 4; c++) acc[a][b][c] = 0.f;

    load_stage(0, 0);
    load_stage(1, 1);
    load_stage(2, 2);

    const int a_r  = lane & 15;
    const int a_kh = lane >> 4;
    const int b_nl = ((lane >> 4) & 1) * 8 + (lane & 7);
    const int b_kh = (lane >> 3) & 1;

    for (int i = 0; i < nchunk; i++) {
        cp_wait2();
        __syncthreads();
        const uint32_t s0 = smem + (i % 3) * STAGE_BYTES;

        #pragma unroll
        for (int kk = 0; kk < 4; kk++) {
            uint32_t ahf[2][4], alf[2][4], bhf[4][4], blf[4][4];
            #pragma unroll
            for (int mt = 0; mt < 2; mt++) {
                const int row = wm * 32 + mt * 16 + a_r;
                const int seg = kk * 2 + a_kh;
                const uint32_t off = (uint32_t)(row * 128 + ((seg ^ (row & 7)) << 4));
                ldm4(ahf[mt], s0 + 0 * TILE_BYTES + off);
                ldm4(alf[mt], s0 + 1 * TILE_BYTES + off);
            }
            #pragma unroll
            for (int p = 0; p < 4; p++) {
                const int row = wn * 64 + p * 16 + b_nl;
                const int seg = kk * 2 + b_kh;
                const uint32_t off = (uint32_t)(row * 128 + ((seg ^ (row & 7)) << 4));
                ldm4(bhf[p], s0 + 2 * TILE_BYTES + off);
                ldm4(blf[p], s0 + 3 * TILE_BYTES + off);
            }
            #pragma unroll
            for (int mt = 0; mt < 2; mt++)
                #pragma unroll
                for (int nt = 0; nt < 8; nt++)
                    mma16816(acc[mt][nt], ahf[mt], &bhf[nt >> 1][(nt & 1) * 2]);
            #pragma unroll
            for (int mt = 0; mt < 2; mt++)
                #pragma unroll
                for (int nt = 0; nt < 8; nt++)
                    mma16816(acc[mt][nt], ahf[mt], &blf[nt >> 1][(nt & 1) * 2]);
            #pragma unroll
            for (int mt = 0; mt < 2; mt++)
                #pragma unroll
                for (int nt = 0; nt < 8; nt++)
                    mma16816(acc[mt][nt], alf[mt], &bhf[nt >> 1][(nt & 1) * 2]);
        }
        __syncthreads();
        load_stage(i % 3, i + 3);
    }

    #pragma unroll
    for (int mt = 0; mt < 2; mt++) {
        #pragma unroll
        for (int h = 0; h < 2; h++) {
            const int row = m0 + wm * 32 + mt * 16 + (lane >> 2) + 8 * h;
            #pragma unroll
            for (int nt = 0; nt < 8; nt++) {
                const int col = n0 + wn * 64 + nt * 8 + (lane & 3) * 2;
                float v0 = acc[mt][nt][2 * h + 0] * scale;
                float v1 = acc[mt][nt][2 * h + 1] * scale;
                if (HAS_BIAS) {
                    const float2 bb = *reinterpret_cast<const float2*>(bias + col);
                    v0 += bb.x; v1 += bb.y;
                }
                if (OUTMODE == 0) {
                    *reinterpret_cast<float2*>(
                        Cf + (size_t)z * sC + (size_t)row * ldC + col) =
                        make_float2(v0, v1);
                } else {
                    float h0 = __bfloat162float(__float2bfloat16(v0));
                    float h1 = __bfloat162float(__float2bfloat16(v1));
                    *reinterpret_cast<uint32_t*>(
                        Ch + (size_t)z * sC + (size_t)row * ldC + col) = pk2(h0, h1);
                    *reinterpret_cast<uint32_t*>(
                        Cl + (size_t)z * sC + (size_t)row * ldC + col) =
                        pk2(v0 - h0, v1 - h1);
                }
            }
        }
    }
}

// ============================================================================
// prep kernels
// ============================================================================
__global__ void split_kernel(const float* __restrict__ in,
                             bf16* __restrict__ oh, bf16* __restrict__ ol, int n)
{
    int i = blockIdx.x * blockDim.x + threadIdx.x;
    if (i >= n) return;
    float v = in[i];
    bf16 h = __float2bfloat16(v);
    oh[i] = h;
    ol[i] = __float2bfloat16(v - __bfloat162float(h));
}

// transpose + split: in [R,C] fp32 -> out hi/lo [C,R] bf16
__global__ void tsplit_kernel(const float* __restrict__ in,
                              bf16* __restrict__ oh, bf16* __restrict__ ol,
                              int R, int C)
{
    __shared__ float t[32][33];
    const int c0 = blockIdx.x * 32, r0 = blockIdx.y * 32;
    const int tx = threadIdx.x, ty = threadIdx.y;
    #pragma unroll
    for (int k = 0; k < 4; k++)
        t[ty + 8 * k][tx] = in[(size_t)(r0 + ty + 8 * k) * C + c0 + tx];
    __syncthreads();
    #pragma unroll
    for (int k = 0; k < 4; k++) {
        float v = t[tx][ty + 8 * k];
        bf16 h = __float2bfloat16(v);
        size_t o = (size_t)(c0 + ty + 8 * k) * R + r0 + tx;
        oh[o] = h;
        ol[o] = __float2bfloat16(v - __bfloat162float(h));
    }
}

// XH transpose+split: reads XH=hi+lo at rows [MROWS + b*SEQ + s], ld=DM;
// writes [b][d][s] split.
__global__ void txsplit_kernel(const bf16* __restrict__ qh, const bf16* __restrict__ ql,
                               bf16* __restrict__ oh, bf16* __restrict__ ol)
{
    __shared__ float t[32][33];
    const int z = blockIdx.z;
    const int d0 = blockIdx.x * 32, s0 = blockIdx.y * 32;
    const int tx = threadIdx.x, ty = threadIdx.y;
    #pragma unroll
    for (int k = 0; k < 4; k++) {
        size_t idx = (size_t)(MROWS + z * SEQ + s0 + ty + 8 * k) * DM + d0 + tx;
        t[ty + 8 * k][tx] = __bfloat162float(qh[idx]) + __bfloat162float(ql[idx]);
    }
    __syncthreads();
    #pragma unroll
    for (int k = 0; k < 4; k++) {
        float v = t[tx][ty + 8 * k];
        bf16 h = __float2bfloat16(v);
        size_t o = (size_t)z * DM * SEQ + (size_t)(d0 + ty + 8 * k) * SEQ + s0 + tx;
        oh[o] = h;
        ol[o] = __float2bfloat16(v - __bfloat162float(h));
    }
}

// w2[d] = sum_e Wk[d,e]*bq[e]   (warp per d)
__global__ void wkbq_kernel(const float* __restrict__ Wk, const float* __restrict__ bq,
                            float* __restrict__ w2)
{
    int w = (blockIdx.x * blockDim.x + threadIdx.x) >> 5;
    int lane = threadIdx.x & 31;
    if (w >= DM) return;
    float s = 0.f;
    for (int e = lane; e < DM; e += 32) s += Wk[(size_t)w * DM + e] * bq[e];
    #pragma unroll
    for (int o = 16; o > 0; o >>= 1) s += __shfl_down_sync(0xffffffffu, s, o);
    if (lane == 0) w2[w] = s;
}

// rb[d] = sum_e bv[e]*Wo[e,d] + bo[d]
__global__ void rb_kernel(const float* __restrict__ Wo, const float* __restrict__ bv,
                          const float* __restrict__ bo, float* __restrict__ rb)
{
    int d = blockIdx.x * blockDim.x + threadIdx.x;
    if (d >= DM) return;
    float s = 0.f;
    for (int e = 0; e < DM; e++) s += bv[e] * Wo[(size_t)e * DM + d];
    rb[d] = s + bo[d];
}

// v[i] = sum_d x[i,d]*w2[d]   (warp per row)
__global__ void vvec_kernel(const float* __restrict__ x, const float* __restrict__ w2,
                            float* __restrict__ v)
{
    int w = (blockIdx.x * blockDim.x + threadIdx.x) >> 5;
    int lane = threadIdx.x & 31;
    if (w >= MROWS) return;
    float s = 0.f;
    for (int d = lane; d < DM; d += 32) s += x[(size_t)w * DM + d] * w2[d];
    #pragma unroll
    for (int o = 16; o > 0; o >>= 1) s += __shfl_down_sync(0xffffffffu, s, o);
    if (lane == 0) v[w] = s;
}

// causal softmax over logits l[k] = p[k] + 0.125*v[b*SEQ+k]; split bf16 out,
// zero-fill tail to next 128 boundary.
__global__ __launch_bounds__(256)
void softmax_split_kernel(float* __restrict__ P, const float* __restrict__ V,
                          bf16* __restrict__ Ph, bf16* __restrict__ Pl)
{
    const int rowi = blockIdx.x;
    const int b = rowi / SEQ, q = rowi % SEQ;
    const size_t off = (size_t)b * SEQ * SEQ + (size_t)q * SEQ;
    float* p = P + off;
    const float* vv = V + (size_t)b * SEQ;
    bf16* ph = Ph + off;
    bf16* pl = Pl + off;
    const int n = q + 1;

    __shared__ float red[256];
    const int tid = threadIdx.x;

    float mx = -CUDART_INF_F;
    for (int k = tid; k < n; k += 256) mx = fmaxf(mx, p[k] + 0.125f * vv[k]);
    red[tid] = mx; __syncthreads();
    #pragma unroll
    for (int s = 128; s > 0; s >>= 1) {
        if (tid < s) red[tid] = fmaxf(red[tid], red[tid + s]);
        __syncthreads();
    }
    mx = red[0]; __syncthreads();

    float sum = 0.f;
    for (int k = tid; k < n; k += 256) {
        float e = expf(p[k] + 0.125f * vv[k] - mx);
        p[k] = e;
        sum += e;
    }
    red[tid] = sum; __syncthreads();
    #pragma unroll
    for (int s = 128; s > 0; s >>= 1) {
        if (tid < s) red[tid] += red[tid + s];
        __syncthreads();
    }
    const float inv = 1.f / red[0];

    for (int k = tid; k < n; k += 256) {
        float w = p[k] * inv;
        bf16 h = __float2bfloat16(w);
        ph[k] = h;
        pl[k] = __float2bfloat16(w - __bfloat162float(h));
    }
    const int fillEnd = ((q >> 7) + 1) << 7;
    for (int k = n + tid; k < fillEnd; k += 256) {
        ph[k] = __float2bfloat16(0.f);
        pl[k] = __float2bfloat16(0.f);
    }
}

// ============================================================================
extern "C" void kernel_launch(void* const* d_in, const int*, int, void* d_out, int)
{
    const float* x  = (const float*)d_in[0];
    const float* Wq = (const float*)d_in[1];
    const float* bq = (const float*)d_in[2];
    const float* Wk = (const float*)d_in[3];
    const float* bk = (const float*)d_in[4];   (void)bk;  // row-constant: cancels in softmax
    const float* Wv = (const float*)d_in[5];
    const float* bv = (const float*)d_in[6];
    const float* Wo = (const float*)d_in[7];
    const float* bo = (const float*)d_in[8];
    float* out = (float*)d_out;

    bf16 *xh, *xl, *wAh, *wAl, *wBh, *wBl, *gh, *gl, *qxh, *qxl, *xth, *xtl, *phh, *pll;
    float *p, *w2, *v, *rb;
    cudaGetSymbolAddress((void**)&xh,  g_xh);  cudaGetSymbolAddress((void**)&xl,  g_xl);
    cudaGetSymbolAddress((void**)&wAh, g_wAh); cudaGetSymbolAddress((void**)&wAl, g_wAl);
    cudaGetSymbolAddress((void**)&wBh, g_wBh); cudaGetSymbolAddress((void**)&wBl, g_wBl);
    cudaGetSymbolAddress((void**)&gh,  g_gh);  cudaGetSymbolAddress((void**)&gl,  g_gl);
    cudaGetSymbolAddress((void**)&qxh, g_qxh); cudaGetSymbolAddress((void**)&qxl, g_qxl);
    cudaGetSymbolAddress((void**)&xth, g_xth); cudaGetSymbolAddress((void**)&xtl, g_xtl);
    cudaGetSymbolAddress((void**)&p,   g_p);
    cudaGetSymbolAddress((void**)&phh, g_ph);  cudaGetSymbolAddress((void**)&pll, g_pl);
    cudaGetSymbolAddress((void**)&w2,  g_w2);  cudaGetSymbolAddress((void**)&v,   g_v);
    cudaGetSymbolAddress((void**)&rb,  g_rb);

    cudaFuncSetAttribute(tc_gemm<1, false, false, false, false>, cudaFuncAttributeMaxDynamicSharedMemorySize, SMEM_DYN);
    cudaFuncSetAttribute(tc_gemm<0, false, true,  false, false>, cudaFuncAttributeMaxDynamicSharedMemorySize, SMEM_DYN);
    cudaFuncSetAttribute(tc_gemm<0, true,  false, true,  true >, cudaFuncAttributeMaxDynamicSharedMemorySize, SMEM_DYN);

    // ---- prep: splits + bias vectors -----------------------------------------
    split_kernel<<<(MROWS * DM + 255) / 256, 256>>>(x, xh, xl, MROWS * DM);
    split_kernel<<<(DM * DM + 255) / 256, 256>>>(Wk, wAh,           wAl,           DM * DM);
    split_kernel<<<(DM * DM + 255) / 256, 256>>>(Wq, wBh,           wBl,           DM * DM);
    split_kernel<<<(DM * DM + 255) / 256, 256>>>(Wv, wBh + DM * DM, wBl + DM * DM, DM * DM);
    {
        dim3 blk(32, 8), grid(DM / 32, DM / 32);
        tsplit_kernel<<<grid, blk>>>(Wo, wAh + DM * DM, wAl + DM * DM, DM, DM);
    }
    wkbq_kernel<<<DM * 32 / 256, 256>>>(Wk, bq, w2);
    rb_kernel<<<DM / 256, 256>>>(Wo, bv, bo, rb);
    vvec_kernel<<<MROWS * 32 / 256, 256>>>(x, w2, v);

    // ---- GT = Wk*Wq^T ; HT = Wo^T*Wv^T-form  (one z=2 batched launch) --------
    {
        dim3 grid(DM / TN, DM / TM, 2), blk(256);
        tc_gemm<1, false, false, false, false><<<grid, blk, SMEM_DYN>>>(
            wAh, wAl, wBh, wBl, nullptr, nullptr, gh, gl,
            DM, DM, DM, DM, 1.f,
            (size_t)DM * DM, (size_t)DM * DM, (size_t)DM * DM);
    }

    // ---- QG = x*GT ; XH = x*HT  (one z=2 batched launch, shared A) -----------
    {
        dim3 grid(DM / TN, MROWS / TM, 2), blk(256);
        tc_gemm<1, false, false, false, false><<<grid, blk, SMEM_DYN>>>(
            xh, xl, gh, gl, nullptr, nullptr, qxh, qxl,
            DM, DM, DM, DM, 1.f,
            0, (size_t)DM * DM, (size_t)MROWS * DM);
    }

    // ---- scores core = 0.125 * QG @ x^T (causal tile skip) -------------------
    {
        dim3 grid(SEQ / TN, SEQ / TM, BATCH), blk(256);
        tc_gemm<0, false, true, false, false><<<grid, blk, SMEM_DYN>>>(
            qxh, qxl, xh, xl, nullptr, p, nullptr, nullptr,
            DM, DM, DM, SEQ, 0.125f,
            (size_t)SEQ * DM, (size_t)SEQ * DM, (size_t)SEQ * SEQ);
    }

    // ---- XH transpose+split: [B][S][D] -> [B][D][S] ----------------------------
    {
        dim3 blk(32, 8), grid(DM / 32, SEQ / 32, BATCH);
        txsplit_kernel<<<grid, blk>>>(qxh, qxl, xth, xtl);
    }

    // ---- softmax over (scores + 0.125*v[j]) -> split bf16 weights --------------
    softmax_split_kernel<<<MROWS, 256>>>(p, v, phh, pll);

    // ---- out = P @ XH + (bv*Wo + bo)  (writes d_out directly) ------------------
    {
        dim3 grid(DM / TN, SEQ / TM, BATCH), blk(256);
        tc_gemm<0, true, false, true, true><<<grid, blk, SMEM_DYN>>>(
            phh, pll, xth, xtl, rb, out, nullptr, nullptr,
            SEQ, SEQ, SEQ, DM, 1.f,
            (size_t)SEQ * SEQ, (size_t)DM * SEQ, (size_t)SEQ * DM);
    }
}

// round 9
// speedup vs baseline: 1.6924x; 1.0077x over previous
#include <cuda_runtime.h>
#include <cuda_fp16.h>
#include <math_constants.h>
#include <stdint.h>

#define BATCH 4
#define SEQ   2048
#define DM    1024
#define MROWS (BATCH * SEQ)

#define LO_SCALE  2048.0f
#define INV_LO    (1.0f / 2048.0f)

// ---- GEMM tiling (proven config) ---------------------------------------------
#define TM 128
#define TN 128
#define BK 64                         // f16 elems per K-chunk (128 bytes/row)
#define TILE_BYTES (128 * 128)        // 16 KB per operand tile
#define STAGE_BYTES (4 * TILE_BYTES)  // Ahi,Alo,Bhi,Blo = 64 KB
#define NSTAGE 3
#define SMEM_DYN (NSTAGE * STAGE_BYTES)   // 192 KB

typedef __half h16;

// ---- scratch (static __device__: allocation-free) ------------------------------
#define AL1K __align__(1024)
__device__ AL1K h16   g_xh [MROWS * DM];
__device__ AL1K h16   g_xl [MROWS * DM];
__device__ AL1K h16   g_wAh[2 * DM * DM];   // [Wk ; Wo^T] split hi
__device__ AL1K h16   g_wAl[2 * DM * DM];
__device__ AL1K h16   g_wBh[2 * DM * DM];   // [Wq ; Wv] split hi
__device__ AL1K h16   g_wBl[2 * DM * DM];
__device__ AL1K h16   g_gh [2 * DM * DM];   // [GT ; HT] split hi
__device__ AL1K h16   g_gl [2 * DM * DM];
__device__ AL1K h16   g_qxh[(size_t)2 * MROWS * DM];  // [QG ; XH] split hi
__device__ AL1K h16   g_qxl[(size_t)2 * MROWS * DM];
__device__ AL1K h16   g_xth[MROWS * DM];    // XH^T per batch [B][D][S]
__device__ AL1K h16   g_xtl[MROWS * DM];
__device__ AL1K float g_p  [(size_t)BATCH * SEQ * SEQ];
__device__ AL1K h16   g_ph [(size_t)BATCH * SEQ * SEQ];
__device__ AL1K h16   g_pl [(size_t)BATCH * SEQ * SEQ];
__device__ AL1K float g_w2 [DM];
__device__ AL1K float g_v  [MROWS];
__device__ AL1K float g_rb [DM];

// ---- PTX helpers -----------------------------------------------------------------
__device__ __forceinline__ uint32_t s2u(const void* p) {
    uint32_t a;
    asm("{ .reg .u64 t; cvta.to.shared.u64 t, %1; cvt.u32.u64 %0, t; }" : "=r"(a) : "l"(p));
    return a;
}
__device__ __forceinline__ void cp16(uint32_t saddr, const void* gaddr) {
    asm volatile("cp.async.cg.shared.global [%0], [%1], 16;" :: "r"(saddr), "l"(gaddr));
}
__device__ __forceinline__ void cp_commit() { asm volatile("cp.async.commit_group;"); }
__device__ __forceinline__ void cp_wait2()  { asm volatile("cp.async.wait_group 2;" ::: "memory"); }

__device__ __forceinline__ void ldm4(uint32_t* r, uint32_t addr) {
    asm volatile("ldmatrix.sync.aligned.m8n8.x4.shared.b16 {%0,%1,%2,%3}, [%4];"
                 : "=r"(r[0]), "=r"(r[1]), "=r"(r[2]), "=r"(r[3]) : "r"(addr));
}
// f16 inputs -> f32 accumulator (main hi*hi term)
__device__ __forceinline__ void mma_f32(float* c, const uint32_t* a, const uint32_t* b) {
    asm volatile(
        "mma.sync.aligned.m16n8k16.row.col.f32.f16.f16.f32 "
        "{%0,%1,%2,%3}, {%4,%5,%6,%7}, {%8,%9}, {%0,%1,%2,%3};"
        : "+f"(c[0]), "+f"(c[1]), "+f"(c[2]), "+f"(c[3])
        : "r"(a[0]), "r"(a[1]), "r"(a[2]), "r"(a[3]), "r"(b[0]), "r"(b[1]));
}
// f16 inputs -> f16 accumulator (correction terms, lo pre-scaled x2048)
__device__ __forceinline__ void mma_f16(uint32_t* c, const uint32_t* a, const uint32_t* b) {
    asm volatile(
        "mma.sync.aligned.m16n8k16.row.col.f16.f16.f16.f16 "
        "{%0,%1}, {%2,%3,%4,%5}, {%6,%7}, {%0,%1};"
        : "+r"(c[0]), "+r"(c[1])
        : "r"(a[0]), "r"(a[1]), "r"(a[2]), "r"(a[3]), "r"(b[0]), "r"(b[1]));
}
__device__ __forceinline__ uint32_t pk2(float a, float b) {
    __half2 t = __floats2half2_rn(a, b);
    return *reinterpret_cast<uint32_t*>(&t);
}

// ============================================================================
// Tensor-core GEMM: C[M,N] = scale*((Ahi+Alo/2048)[M,K] @ ((Bhi+Blo/2048)[N,K])^T)+bias
//   hi*hi in f32 acc; (hi*lo' + lo'*hi) in shared f16 acc, descaled /2048.
//   OUTMODE 0: fp32 out (Cf).  OUTMODE 1: f16 split out (Ch, Cl; lo x2048).
//   CAUSAL: skip 128x128 tiles strictly above diagonal.
//   PVLIM : K truncated at causal boundary.  REVY: heavy CTAs first.
// ============================================================================
template<int OUTMODE, bool HAS_BIAS, bool CAUSAL, bool PVLIM, bool REVY>
__global__ __launch_bounds__(256, 1)
void tc_gemm(const h16* __restrict__ Ah, const h16* __restrict__ Al,
             const h16* __restrict__ Bh, const h16* __restrict__ Bl,
             const float* __restrict__ bias,
             float* __restrict__ Cf, h16* __restrict__ Ch, h16* __restrict__ Cl,
             int Kfull, int ldA, int ldB, int ldC, float scale,
             size_t sA, size_t sB, size_t sC)
{
    const int bmi = REVY ? (gridDim.y - 1 - blockIdx.y) : blockIdx.y;
    const int m0 = bmi * TM;
    const int n0 = blockIdx.x * TN;
    if (CAUSAL && n0 > m0) return;

    const int z = blockIdx.z;
    Ah += (size_t)z * sA;  Al += (size_t)z * sA;
    Bh += (size_t)z * sB;  Bl += (size_t)z * sB;

    extern __shared__ char dsm[];
    const uint32_t smem = s2u(dsm);

    const int tid  = threadIdx.x;
    const int wid  = tid >> 5;
    const int lane = tid & 31;
    const int wm   = wid & 3;    // 4 warp-rows  (32 M each)
    const int wn   = wid >> 2;   // 2 warp-cols  (64 N each)

    const int nchunk = PVLIM ? (m0 + TM) / BK : Kfull / BK;

    const int lrow = tid >> 1;
    const int sb   = (tid & 1) * 4;
    const char* gp[4];
    uint32_t    so[4][4];
    {
        const h16* bases[4] = {Ah, Al, Bh, Bl};
        #pragma unroll
        for (int t = 0; t < 4; t++) {
            const int off = (t < 2) ? m0 : n0;
            const int ld  = (t < 2) ? ldA : ldB;
            gp[t] = (const char*)(bases[t] + (size_t)(off + lrow) * ld);
            #pragma unroll
            for (int j = 0; j < 4; j++) {
                const int seg = sb + j;
                so[t][j] = (uint32_t)(t * TILE_BYTES + lrow * 128 +
                                      ((seg ^ (lrow & 7)) << 4));
            }
        }
    }

    auto load_stage = [&](int slot, int chunk) {
        if (chunk < nchunk) {
            const uint32_t s0 = smem + slot * STAGE_BYTES;
            const size_t goff = (size_t)chunk * 128;
            #pragma unroll
            for (int t = 0; t < 4; t++) {
                #pragma unroll
                for (int j = 0; j < 4; j++)
                    cp16(s0 + so[t][j], gp[t] + goff + (size_t)(sb + j) * 16);
            }
        }
        cp_commit();
    };

    float    accf[2][8][4];
    uint32_t acch[2][8][2];
    #pragma unroll
    for (int a = 0; a < 2; a++)
        #pragma unroll
        for (int b = 0; b < 8; b++) {
            #pragma unroll
            for (int c = 0; c < 4; c++) accf[a][b][c] = 0.f;
            acch[a][b][0] = 0u; acch[a][b][1] = 0u;
        }

    load_stage(0, 0);
    load_stage(1, 1);
    load_stage(2, 2);

    const int a_r  = lane & 15;
    const int a_kh = lane >> 4;
    const int b_nl = ((lane >> 4) & 1) * 8 + (lane & 7);
    const int b_kh = (lane >> 3) & 1;

    for (int i = 0; i < nchunk; i++) {
        cp_wait2();
        __syncthreads();
        const uint32_t s0 = smem + (i % 3) * STAGE_BYTES;

        #pragma unroll
        for (int kk = 0; kk < 4; kk++) {
            uint32_t ahf[2][4], alf[2][4], bhf[4][4], blf[4][4];
            #pragma unroll
            for (int mt = 0; mt < 2; mt++) {
                const int row = wm * 32 + mt * 16 + a_r;
                const int seg = kk * 2 + a_kh;
                const uint32_t off = (uint32_t)(row * 128 + ((seg ^ (row & 7)) << 4));
                ldm4(ahf[mt], s0 + 0 * TILE_BYTES + off);
                ldm4(alf[mt], s0 + 1 * TILE_BYTES + off);
            }
            #pragma unroll
            for (int p = 0; p < 4; p++) {
                const int row = wn * 64 + p * 16 + b_nl;
                const int seg = kk * 2 + b_kh;
                const uint32_t off = (uint32_t)(row * 128 + ((seg ^ (row & 7)) << 4));
                ldm4(bhf[p], s0 + 2 * TILE_BYTES + off);
                ldm4(blf[p], s0 + 3 * TILE_BYTES + off);
            }
            // main term (f32 acc)
            #pragma unroll
            for (int mt = 0; mt < 2; mt++)
                #pragma unroll
                for (int nt = 0; nt < 8; nt++)
                    mma_f32(accf[mt][nt], ahf[mt], &bhf[nt >> 1][(nt & 1) * 2]);
            // correction terms (f16 acc; lo operands pre-scaled x2048)
            #pragma unroll
            for (int mt = 0; mt < 2; mt++)
                #pragma unroll
                for (int nt = 0; nt < 8; nt++)
                    mma_f16(acch[mt][nt], ahf[mt], &blf[nt >> 1][(nt & 1) * 2]);
            #pragma unroll
            for (int mt = 0; mt < 2; mt++)
                #pragma unroll
                for (int nt = 0; nt < 8; nt++)
                    mma_f16(acch[mt][nt], alf[mt], &bhf[nt >> 1][(nt & 1) * 2]);
        }
        __syncthreads();
        load_stage(i % 3, i + 3);
    }

    #pragma unroll
    for (int mt = 0; mt < 2; mt++) {
        #pragma unroll
        for (int h = 0; h < 2; h++) {
            const int row = m0 + wm * 32 + mt * 16 + (lane >> 2) + 8 * h;
            #pragma unroll
            for (int nt = 0; nt < 8; nt++) {
                const int col = n0 + wn * 64 + nt * 8 + (lane & 3) * 2;
                const __half2 hc = *reinterpret_cast<const __half2*>(&acch[mt][nt][h]);
                float v0 = (accf[mt][nt][2 * h + 0] + __low2float(hc)  * INV_LO) * scale;
                float v1 = (accf[mt][nt][2 * h + 1] + __high2float(hc) * INV_LO) * scale;
                if (HAS_BIAS) {
                    const float2 bb = *reinterpret_cast<const float2*>(bias + col);
                    v0 += bb.x; v1 += bb.y;
                }
                if (OUTMODE == 0) {
                    *reinterpret_cast<float2*>(
                        Cf + (size_t)z * sC + (size_t)row * ldC + col) =
                        make_float2(v0, v1);
                } else {
                    float h0 = __half2float(__float2half_rn(v0));
                    float h1 = __half2float(__float2half_rn(v1));
                    *reinterpret_cast<uint32_t*>(
                        Ch + (size_t)z * sC + (size_t)row * ldC + col) = pk2(h0, h1);
                    *reinterpret_cast<uint32_t*>(
                        Cl + (size_t)z * sC + (size_t)row * ldC + col) =
                        pk2((v0 - h0) * LO_SCALE, (v1 - h1) * LO_SCALE);
                }
            }
        }
    }
}

// ============================================================================
// prep kernels (all lo outputs pre-scaled x2048)
// ============================================================================
__global__ void split_kernel(const float* __restrict__ in,
                             h16* __restrict__ oh, h16* __restrict__ ol, int n)
{
    int i = blockIdx.x * blockDim.x + threadIdx.x;
    if (i >= n) return;
    float v = in[i];
    h16 h = __float2half_rn(v);
    oh[i] = h;
    ol[i] = __float2half_rn((v - __half2float(h)) * LO_SCALE);
}

__global__ void tsplit_kernel(const float* __restrict__ in,
                              h16* __restrict__ oh, h16* __restrict__ ol,
                              int R, int C)
{
    __shared__ float t[32][33];
    const int c0 = blockIdx.x * 32, r0 = blockIdx.y * 32;
    const int tx = threadIdx.x, ty = threadIdx.y;
    #pragma unroll
    for (int k = 0; k < 4; k++)
        t[ty + 8 * k][tx] = in[(size_t)(r0 + ty + 8 * k) * C + c0 + tx];
    __syncthreads();
    #pragma unroll
    for (int k = 0; k < 4; k++) {
        float v = t[tx][ty + 8 * k];
        h16 h = __float2half_rn(v);
        size_t o = (size_t)(c0 + ty + 8 * k) * R + r0 + tx;
        oh[o] = h;
        ol[o] = __float2half_rn((v - __half2float(h)) * LO_SCALE);
    }
}

// XH transpose+split: reads XH = hi + lo/2048 at rows [MROWS + b*SEQ + s], ld=DM
__global__ void txsplit_kernel(const h16* __restrict__ qh, const h16* __restrict__ ql,
                               h16* __restrict__ oh, h16* __restrict__ ol)
{
    __shared__ float t[32][33];
    const int z = blockIdx.z;
    const int d0 = blockIdx.x * 32, s0 = blockIdx.y * 32;
    const int tx = threadIdx.x, ty = threadIdx.y;
    #pragma unroll
    for (int k = 0; k < 4; k++) {
        size_t idx = (size_t)(MROWS + z * SEQ + s0 + ty + 8 * k) * DM + d0 + tx;
        t[ty + 8 * k][tx] = __half2float(qh[idx]) + __half2float(ql[idx]) * INV_LO;
    }
    __syncthreads();
    #pragma unroll
    for (int k = 0; k < 4; k++) {
        float v = t[tx][ty + 8 * k];
        h16 h = __float2half_rn(v);
        size_t o = (size_t)z * DM * SEQ + (size_t)(d0 + ty + 8 * k) * SEQ + s0 + tx;
        oh[o] = h;
        ol[o] = __float2half_rn((v - __half2float(h)) * LO_SCALE);
    }
}

__global__ void wkbq_kernel(const float* __restrict__ Wk, const float* __restrict__ bq,
                            float* __restrict__ w2)
{
    int w = (blockIdx.x * blockDim.x + threadIdx.x) >> 5;
    int lane = threadIdx.x & 31;
    if (w >= DM) return;
    float s = 0.f;
    for (int e = lane; e < DM; e += 32) s += Wk[(size_t)w * DM + e] * bq[e];
    #pragma unroll
    for (int o = 16; o > 0; o >>= 1) s += __shfl_down_sync(0xffffffffu, s, o);
    if (lane == 0) w2[w] = s;
}

__global__ void rb_kernel(const float* __restrict__ Wo, const float* __restrict__ bv,
                          const float* __restrict__ bo, float* __restrict__ rb)
{
    int d = blockIdx.x * blockDim.x + threadIdx.x;
    if (d >= DM) return;
    float s = 0.f;
    for (int e = 0; e < DM; e++) s += bv[e] * Wo[(size_t)e * DM + d];
    rb[d] = s + bo[d];
}

__global__ void vvec_kernel(const float* __restrict__ x, const float* __restrict__ w2,
                            float* __restrict__ v)
{
    int w = (blockIdx.x * blockDim.x + threadIdx.x) >> 5;
    int lane = threadIdx.x & 31;
    if (w >= MROWS) return;
    float s = 0.f;
    for (int d = lane; d < DM; d += 32) s += x[(size_t)w * DM + d] * w2[d];
    #pragma unroll
    for (int o = 16; o > 0; o >>= 1) s += __shfl_down_sync(0xffffffffu, s, o);
    if (lane == 0) v[w] = s;
}

__global__ __launch_bounds__(256)
void softmax_split_kernel(float* __restrict__ P, const float* __restrict__ V,
                          h16* __restrict__ Ph, h16* __restrict__ Pl)
{
    const int rowi = blockIdx.x;
    const int b = rowi / SEQ, q = rowi % SEQ;
    const size_t off = (size_t)b * SEQ * SEQ + (size_t)q * SEQ;
    float* p = P + off;
    const float* vv = V + (size_t)b * SEQ;
    h16* ph = Ph + off;
    h16* pl = Pl + off;
    const int n = q + 1;

    __shared__ float red[256];
    const int tid = threadIdx.x;

    float mx = -CUDART_INF_F;
    for (int k = tid; k < n; k += 256) mx = fmaxf(mx, p[k] + 0.125f * vv[k]);
    red[tid] = mx; __syncthreads();
    #pragma unroll
    for (int s = 128; s > 0; s >>= 1) {
        if (tid < s) red[tid] = fmaxf(red[tid], red[tid + s]);
        __syncthreads();
    }
    mx = red[0]; __syncthreads();

    float sum = 0.f;
    for (int k = tid; k < n; k += 256) {
        float e = expf(p[k] + 0.125f * vv[k] - mx);
        p[k] = e;
        sum += e;
    }
    red[tid] = sum; __syncthreads();
    #pragma unroll
    for (int s = 128; s > 0; s >>= 1) {
        if (tid < s) red[tid] += red[tid + s];
        __syncthreads();
    }
    const float inv = 1.f / red[0];

    for (int k = tid; k < n; k += 256) {
        float w = p[k] * inv;
        h16 h = __float2half_rn(w);
        ph[k] = h;
        pl[k] = __float2half_rn((w - __half2float(h)) * LO_SCALE);
    }
    const int fillEnd = ((q >> 7) + 1) << 7;
    for (int k = n + tid; k < fillEnd; k += 256) {
        ph[k] = __float2half_rn(0.f);
        pl[k] = __float2half_rn(0.f);
    }
}

// ============================================================================
extern "C" void kernel_launch(void* const* d_in, const int*, int, void* d_out, int)
{
    const float* x  = (const float*)d_in[0];
    const float* Wq = (const float*)d_in[1];
    const float* bq = (const float*)d_in[2];
    const float* Wk = (const float*)d_in[3];
    const float* bk = (const float*)d_in[4];   (void)bk;  // cancels in softmax
    const float* Wv = (const float*)d_in[5];
    const float* bv = (const float*)d_in[6];
    const float* Wo = (const float*)d_in[7];
    const float* bo = (const float*)d_in[8];
    float* out = (float*)d_out;

    h16 *xh, *xl, *wAh, *wAl, *wBh, *wBl, *gh, *gl, *qxh, *qxl, *xth, *xtl, *phh, *pll;
    float *p, *w2, *v, *rb;
    cudaGetSymbolAddress((void**)&xh,  g_xh);  cudaGetSymbolAddress((void**)&xl,  g_xl);
    cudaGetSymbolAddress((void**)&wAh, g_wAh); cudaGetSymbolAddress((void**)&wAl, g_wAl);
    cudaGetSymbolAddress((void**)&wBh, g_wBh); cudaGetSymbolAddress((void**)&wBl, g_wBl);
    cudaGetSymbolAddress((void**)&gh,  g_gh);  cudaGetSymbolAddress((void**)&gl,  g_gl);
    cudaGetSymbolAddress((void**)&qxh, g_qxh); cudaGetSymbolAddress((void**)&qxl, g_qxl);
    cudaGetSymbolAddress((void**)&xth, g_xth); cudaGetSymbolAddress((void**)&xtl, g_xtl);
    cudaGetSymbolAddress((void**)&p,   g_p);
    cudaGetSymbolAddress((void**)&phh, g_ph);  cudaGetSymbolAddress((void**)&pll, g_pl);
    cudaGetSymbolAddress((void**)&w2,  g_w2);  cudaGetSymbolAddress((void**)&v,   g_v);
    cudaGetSymbolAddress((void**)&rb,  g_rb);

    cudaFuncSetAttribute(tc_gemm<1, false, false, false, false>, cudaFuncAttributeMaxDynamicSharedMemorySize, SMEM_DYN);
    cudaFuncSetAttribute(tc_gemm<0, false, true,  false, false>, cudaFuncAttributeMaxDynamicSharedMemorySize, SMEM_DYN);
    cudaFuncSetAttribute(tc_gemm<0, true,  false, true,  true >, cudaFuncAttributeMaxDynamicSharedMemorySize, SMEM_DYN);

    // ---- prep: splits + bias vectors ---------------------------------------
    split_kernel<<<(MROWS * DM + 255) / 256, 256>>>(x, xh, xl, MROWS * DM);
    split_kernel<<<(DM * DM + 255) / 256, 256>>>(Wk, wAh,           wAl,           DM * DM);
    split_kernel<<<(DM * DM + 255) / 256, 256>>>(Wq, wBh,           wBl,           DM * DM);
    split_kernel<<<(DM * DM + 255) / 256, 256>>>(Wv, wBh + DM * DM, wBl + DM * DM, DM * DM);
    {
        dim3 blk(32, 8), grid(DM / 32, DM / 32);
        tsplit_kernel<<<grid, blk>>>(Wo, wAh + DM * DM, wAl + DM * DM, DM, DM);
    }
    wkbq_kernel<<<DM * 32 / 256, 256>>>(Wk, bq, w2);
    rb_kernel<<<DM / 256, 256>>>(Wo, bv, bo, rb);
    vvec_kernel<<<MROWS * 32 / 256, 256>>>(x, w2, v);

    // ---- GT = Wk*Wq^T ; HT = Wo^T*Wv^T-form (one z=2 batched launch) --------
    {
        dim3 grid(DM / TN, DM / TM, 2), blk(256);
        tc_gemm<1, false, false, false, false><<<grid, blk, SMEM_DYN>>>(
            wAh, wAl, wBh, wBl, nullptr, nullptr, gh, gl,
            DM, DM, DM, DM, 1.f,
            (size_t)DM * DM, (size_t)DM * DM, (size_t)DM * DM);
    }

    // ---- QG = x*GT ; XH = x*HT (one z=2 batched launch, shared A) ------------
    {
        dim3 grid(DM / TN, MROWS / TM, 2), blk(256);
        tc_gemm<1, false, false, false, false><<<grid, blk, SMEM_DYN>>>(
            xh, xl, gh, gl, nullptr, nullptr, qxh, qxl,
            DM, DM, DM, DM, 1.f,
            0, (size_t)DM * DM, (size_t)MROWS * DM);
    }

    // ---- scores core = 0.125 * QG @ x^T (causal tile skip) -------------------
    {
        dim3 grid(SEQ / TN, SEQ / TM, BATCH), blk(256);
        tc_gemm<0, false, true, false, false><<<grid, blk, SMEM_DYN>>>(
            qxh, qxl, xh, xl, nullptr, p, nullptr, nullptr,
            DM, DM, DM, SEQ, 0.125f,
            (size_t)SEQ * DM, (size_t)SEQ * DM, (size_t)SEQ * SEQ);
    }

    // ---- XH transpose+split: [B][S][D] -> [B][D][S] ---------------------------
    {
        dim3 blk(32, 8), grid(DM / 32, SEQ / 32, BATCH);
        txsplit_kernel<<<grid, blk>>>(qxh, qxl, xth, xtl);
    }

    // ---- softmax over (scores + 0.125*v[j]) -> split f16 weights --------------
    softmax_split_kernel<<<MROWS, 256>>>(p, v, phh, pll);

    // ---- out = P @ XH + (bv*Wo + bo)  (writes d_out directly) -----------------
    {
        dim3 grid(DM / TN, SEQ / TM, BATCH), blk(256);
        tc_gemm<0, true, false, true, true><<<grid, blk, SMEM_DYN>>>(
            phh, pll, xth, xtl, rb, out, nullptr, nullptr,
            SEQ, SEQ, SEQ, DM, 1.f,
            (size_t)SEQ * SEQ, (size_t)DM * SEQ, (size_t)SEQ * DM);
    }
}